// round 1
// baseline (speedup 1.0000x reference)
#include <cuda_runtime.h>
#include <cuda_bf16.h>
#include <math.h>

// ---------------------------------------------------------------------------
// MTCNN ONet forward, N=2048, fp32 direct convolutions.
// Stages:
//  K1: conv1(3->32,3x3)+PReLU+maxpool(3,2,ceil)  48x48 -> 23x23   -> g_B1
//  K2: conv2(32->64,3x3)+PReLU                   23x23 -> 21x21   -> g_C2
//  K3: maxpool(3,2)                              21x21 -> 10x10   -> g_B2
//  K4: conv3(64->64,3x3)+PReLU                   10x10 -> 8x8     -> g_C3
//  K5: maxpool(2,2)                              8x8   -> 4x4     -> g_B3
//  K6: conv4(64->128,2x2)+PReLU+permute flatten  4x4   -> 1152    -> g_B4
//  K7: fc5 (1152->256)+PReLU (tiled GEMM)                          -> g_B5
//  K8: heads 256->{2 softmax, 4, 10}, write d_out [b|c|a]
// ---------------------------------------------------------------------------

#define NIMG 2048

__device__ float g_B1[(size_t)NIMG * 32 * 23 * 23];  // pool1 out
__device__ float g_C2[(size_t)NIMG * 64 * 21 * 21];  // conv2 out
__device__ float g_B2[(size_t)NIMG * 64 * 10 * 10];  // pool2 out
__device__ float g_C3[(size_t)NIMG * 64 * 8 * 8];    // conv3 out
__device__ float g_B3[(size_t)NIMG * 64 * 4 * 4];    // pool3 out
__device__ float g_B4[(size_t)NIMG * 1152];          // conv4 flat
__device__ float g_B5[(size_t)NIMG * 256];           // fc5 out

#define NEG_INF (-1e30f)

// ---------------------------------------------------------------------------
// K1: conv1 + PReLU + maxpool(3,2,ceil): in [3,48,48] -> out [32,23,23]
// One block per image. Task = (oc, pooled row py). Horizontal sliding max
// via c_prev register; conv pair shares input loads.
// ---------------------------------------------------------------------------
__global__ __launch_bounds__(256) void k1_conv1_pool(
    const float* __restrict__ x, const float* __restrict__ w,
    const float* __restrict__ bias, const float* __restrict__ alpha)
{
    __shared__ float s_in[3 * 48 * 48 + 8];
    __shared__ float s_w[32 * 27];
    __shared__ float s_b[32];
    __shared__ float s_a[32];

    const int n = blockIdx.x;
    const float* xin = x + (size_t)n * 3 * 48 * 48;
    for (int i = threadIdx.x; i < 3 * 48 * 48; i += 256) s_in[i] = xin[i];
    if (threadIdx.x < 8) s_in[3 * 48 * 48 + threadIdx.x] = 0.f;
    for (int i = threadIdx.x; i < 32 * 27; i += 256) s_w[i] = w[i];
    if (threadIdx.x < 32) {
        s_b[threadIdx.x] = bias[threadIdx.x];
        s_a[threadIdx.x] = alpha[threadIdx.x];
    }
    __syncthreads();

    for (int t = threadIdx.x; t < 32 * 23; t += 256) {
        const int oc = t / 23;
        const int py = t % 23;
        float wr[27];
#pragma unroll
        for (int i = 0; i < 27; i++) wr[i] = s_w[oc * 27 + i];
        const float b0 = s_b[oc];
        const float al = s_a[oc];

        // conv pair at (cy, cx) and (cy, cx+1), pre-activation
        auto conv_pair = [&](int cy, int cx, float& v0, float& v1) {
            v0 = b0; v1 = b0;
#pragma unroll
            for (int ic = 0; ic < 3; ic++) {
#pragma unroll
                for (int ky = 0; ky < 3; ky++) {
                    const float* r = s_in + ic * 2304 + (cy + ky) * 48 + cx;
                    float x0 = r[0], x1 = r[1], x2 = r[2], x3 = r[3];
                    float w0 = wr[ic * 9 + ky * 3 + 0];
                    float w1 = wr[ic * 9 + ky * 3 + 1];
                    float w2 = wr[ic * 9 + ky * 3 + 2];
                    v0 += x0 * w0 + x1 * w1 + x2 * w2;
                    v1 += x1 * w0 + x2 * w1 + x3 * w2;
                }
            }
        };
        auto act = [&](float v) { return v >= 0.f ? v : al * v; };

        float cprev[3];
        bool rowok[3];
#pragma unroll
        for (int r = 0; r < 3; r++) {
            const int cy = 2 * py + r;
            rowok[r] = (cy < 46);
            if (rowok[r]) {
                float v0, v1;
                conv_pair(cy, 0, v0, v1);
                cprev[r] = act(v0);
            } else {
                cprev[r] = NEG_INF;
            }
        }

        float* orow = g_B1 + ((size_t)n * 32 + oc) * 529 + py * 23;
        for (int px = 0; px < 23; px++) {
            const int cx = 2 * px + 1;       // conv col of first new value
            const bool c2ok = (cx + 1) < 46; // second new value valid?
            float m = NEG_INF;
#pragma unroll
            for (int r = 0; r < 3; r++) {
                if (rowok[r]) {
                    float v0, v1;
                    conv_pair(2 * py + r, cx, v0, v1);
                    v0 = act(v0);
                    float mm = fmaxf(cprev[r], v0);
                    if (c2ok) {
                        v1 = act(v1);
                        mm = fmaxf(mm, v1);
                        cprev[r] = v1;
                    }
                    m = fmaxf(m, mm);
                }
            }
            orow[px] = m;
        }
    }
}

// ---------------------------------------------------------------------------
// K2: conv2 (32->64, 3x3) + PReLU: in [32,23,23] -> out [64,21,21]
// One block per image. Dyn smem: input + all weights. Microkernel 8oc x 8px.
// ---------------------------------------------------------------------------
#define K2_SMEM_FLOATS (16928 + 18432 + 64 + 64)
__global__ __launch_bounds__(256, 1) void k2_conv2(
    const float* __restrict__ w, const float* __restrict__ bias,
    const float* __restrict__ alpha)
{
    extern __shared__ float sm2[];
    float* s_in = sm2;              // 32*529
    float* s_w  = sm2 + 16928;      // 64*32*9
    float* s_b  = s_w + 18432;      // 64
    float* s_a  = s_b + 64;         // 64

    const int n = blockIdx.x;
    {
        const float4* src = (const float4*)(g_B1 + (size_t)n * 16928);
        float4* dst = (float4*)s_in;
        for (int i = threadIdx.x; i < 16928 / 4; i += 256) dst[i] = src[i];
        const float4* ws = (const float4*)w;
        float4* wd = (float4*)s_w;
        for (int i = threadIdx.x; i < 18432 / 4; i += 256) wd[i] = ws[i];
        if (threadIdx.x < 64) {
            s_b[threadIdx.x] = bias[threadIdx.x];
            s_a[threadIdx.x] = alpha[threadIdx.x];
        }
    }
    __syncthreads();

    float* ob = g_C2 + (size_t)n * 64 * 441;

    for (int t = threadIdx.x; t < 504; t += 256) {
        const int ocg = t / 63;
        const int rem = t % 63;
        const int y = rem / 3;
        const int xg = (rem % 3) * 8;

        float acc[8][8];
#pragma unroll
        for (int o = 0; o < 8; o++)
#pragma unroll
            for (int j = 0; j < 8; j++) acc[o][j] = 0.f;

        for (int ic = 0; ic < 32; ic++) {
#pragma unroll
            for (int ky = 0; ky < 3; ky++) {
                const float* row = s_in + ic * 529 + (y + ky) * 23;
                float xi[10];
#pragma unroll
                for (int j = 0; j < 10; j++) {
                    int c = xg + j;
                    xi[j] = row[c > 22 ? 22 : c];  // clamp (dead lanes only)
                }
#pragma unroll
                for (int o = 0; o < 8; o++) {
                    const float* wp = s_w + ((ocg * 8 + o) * 32 + ic) * 9 + ky * 3;
                    float w0 = wp[0], w1 = wp[1], w2 = wp[2];
#pragma unroll
                    for (int j = 0; j < 8; j++)
                        acc[o][j] += xi[j] * w0 + xi[j + 1] * w1 + xi[j + 2] * w2;
                }
            }
        }
#pragma unroll
        for (int o = 0; o < 8; o++) {
            const int oc = ocg * 8 + o;
            const float b0 = s_b[oc], al = s_a[oc];
#pragma unroll
            for (int j = 0; j < 8; j++) {
                const int xx = xg + j;
                if (xx < 21) {
                    float v = acc[o][j] + b0;
                    v = v >= 0.f ? v : al * v;
                    ob[oc * 441 + y * 21 + xx] = v;
                }
            }
        }
    }
}

// ---------------------------------------------------------------------------
// K3: maxpool 3,2 on 21x21 -> 10x10 (no padding needed: 9*2+3=21)
// ---------------------------------------------------------------------------
__global__ __launch_bounds__(256) void k3_pool2()
{
    const int idx = blockIdx.x * 256 + threadIdx.x;  // exact grid
    const int px = idx % 10;
    const int py = (idx / 10) % 10;
    const int nc = idx / 100;  // n*64 + c
    const float* base = g_C2 + (size_t)nc * 441;
    float m = NEG_INF;
#pragma unroll
    for (int ky = 0; ky < 3; ky++)
#pragma unroll
        for (int kx = 0; kx < 3; kx++)
            m = fmaxf(m, base[(py * 2 + ky) * 21 + (px * 2 + kx)]);
    g_B2[idx] = m;
}

// ---------------------------------------------------------------------------
// K4: conv3 (64->64, 3x3) + PReLU: [64,10,10] -> [64,8,8]
// 4 images per block, weights in 2 oc-chunks, microkernel 4oc x 8px.
// ---------------------------------------------------------------------------
#define K4_SMEM_FLOATS (25600 + 18432 + 64 + 64)
__global__ __launch_bounds__(256, 1) void k4_conv3(
    const float* __restrict__ w, const float* __restrict__ bias,
    const float* __restrict__ alpha)
{
    extern __shared__ float sm4[];
    float* s_in = sm4;             // 4*64*100
    float* s_w  = sm4 + 25600;     // 32*64*9
    float* s_b  = s_w + 18432;
    float* s_a  = s_b + 64;

    const int n0 = blockIdx.x * 4;
    {
        const float4* src = (const float4*)(g_B2 + (size_t)n0 * 6400);
        float4* dst = (float4*)s_in;
        for (int i = threadIdx.x; i < 25600 / 4; i += 256) dst[i] = src[i];
        if (threadIdx.x < 64) {
            s_b[threadIdx.x] = bias[threadIdx.x];
            s_a[threadIdx.x] = alpha[threadIdx.x];
        }
    }

    const int t = threadIdx.x;
    const int img = t >> 6;
    const int ocg = (t & 63) >> 3;
    const int y = t & 7;

    for (int chunk = 0; chunk < 2; chunk++) {
        if (chunk) __syncthreads();  // prev compute done before w overwrite
        {
            const float4* ws = (const float4*)(w + chunk * 32 * 576);
            float4* wd = (float4*)s_w;
            for (int i = threadIdx.x; i < 18432 / 4; i += 256) wd[i] = ws[i];
        }
        __syncthreads();

        float acc[4][8];
#pragma unroll
        for (int o = 0; o < 4; o++)
#pragma unroll
            for (int j = 0; j < 8; j++) acc[o][j] = 0.f;

        for (int ic = 0; ic < 64; ic++) {
#pragma unroll
            for (int ky = 0; ky < 3; ky++) {
                const float* row = s_in + img * 6400 + ic * 100 + (y + ky) * 10;
                float xi[10];
#pragma unroll
                for (int j = 0; j < 10; j++) xi[j] = row[j];
#pragma unroll
                for (int o = 0; o < 4; o++) {
                    const float* wp = s_w + ((ocg * 4 + o) * 64 + ic) * 9 + ky * 3;
                    float w0 = wp[0], w1 = wp[1], w2 = wp[2];
#pragma unroll
                    for (int j = 0; j < 8; j++)
                        acc[o][j] += xi[j] * w0 + xi[j + 1] * w1 + xi[j + 2] * w2;
                }
            }
        }
#pragma unroll
        for (int o = 0; o < 4; o++) {
            const int oc = chunk * 32 + ocg * 4 + o;
            const float b0 = s_b[oc], al = s_a[oc];
            float* orow = g_C3 + ((size_t)(n0 + img) * 64 + oc) * 64 + y * 8;
#pragma unroll
            for (int j = 0; j < 8; j++) {
                float v = acc[o][j] + b0;
                orow[j] = v >= 0.f ? v : al * v;
            }
        }
    }
}

// ---------------------------------------------------------------------------
// K5: maxpool 2,2 on 8x8 -> 4x4
// ---------------------------------------------------------------------------
__global__ __launch_bounds__(256) void k5_pool3()
{
    const int idx = blockIdx.x * 256 + threadIdx.x;  // exact grid
    const int px = idx % 4;
    const int py = (idx / 4) % 4;
    const int nc = idx / 16;
    const float* base = g_C3 + (size_t)nc * 64;
    float m = fmaxf(fmaxf(base[(py * 2) * 8 + px * 2], base[(py * 2) * 8 + px * 2 + 1]),
                    fmaxf(base[(py * 2 + 1) * 8 + px * 2], base[(py * 2 + 1) * 8 + px * 2 + 1]));
    g_B3[idx] = m;
}

// ---------------------------------------------------------------------------
// K6: conv4 (64->128, 2x2) + PReLU + permute(0,3,2,1) flatten -> [N,1152]
// 16 images per block, all weights in smem.
// flat index f = w*384 + h*128 + oc
// ---------------------------------------------------------------------------
#define K6_SMEM_FLOATS (16384 + 32768 + 128 + 128)
__global__ __launch_bounds__(256, 1) void k6_conv4(
    const float* __restrict__ w, const float* __restrict__ bias,
    const float* __restrict__ alpha)
{
    extern __shared__ float sm6[];
    float* s_in = sm6;             // 16*64*16
    float* s_w  = sm6 + 16384;     // 128*64*4
    float* s_b  = s_w + 32768;
    float* s_a  = s_b + 128;

    const int n0 = blockIdx.x * 16;
    {
        const float4* src = (const float4*)(g_B3 + (size_t)n0 * 1024);
        float4* dst = (float4*)s_in;
        for (int i = threadIdx.x; i < 16384 / 4; i += 256) dst[i] = src[i];
        const float4* ws = (const float4*)w;
        float4* wd = (float4*)s_w;
        for (int i = threadIdx.x; i < 32768 / 4; i += 256) wd[i] = ws[i];
        if (threadIdx.x < 128) {
            s_b[threadIdx.x] = bias[threadIdx.x];
            s_a[threadIdx.x] = alpha[threadIdx.x];
        }
    }
    __syncthreads();

    for (int t = threadIdx.x; t < 16 * 128; t += 256) {
        const int img = t >> 7;
        const int oc = t & 127;
        float acc[9];
#pragma unroll
        for (int i = 0; i < 9; i++) acc[i] = 0.f;

        for (int ic = 0; ic < 64; ic++) {
            const float* ib = s_in + img * 1024 + ic * 16;
            float xi[16];
#pragma unroll
            for (int i = 0; i < 16; i++) xi[i] = ib[i];
            const float* wp = s_w + (oc * 64 + ic) * 4;
            float w00 = wp[0], w01 = wp[1], w10 = wp[2], w11 = wp[3];
#pragma unroll
            for (int h = 0; h < 3; h++)
#pragma unroll
                for (int ww = 0; ww < 3; ww++)
                    acc[h * 3 + ww] += xi[h * 4 + ww] * w00 + xi[h * 4 + ww + 1] * w01 +
                                       xi[(h + 1) * 4 + ww] * w10 + xi[(h + 1) * 4 + ww + 1] * w11;
        }
        const float b0 = s_b[oc], al = s_a[oc];
        float* ob = g_B4 + (size_t)(n0 + img) * 1152;
#pragma unroll
        for (int h = 0; h < 3; h++)
#pragma unroll
            for (int ww = 0; ww < 3; ww++) {
                float v = acc[h * 3 + ww] + b0;
                v = v >= 0.f ? v : al * v;
                ob[ww * 384 + h * 128 + oc] = v;
            }
    }
}

// ---------------------------------------------------------------------------
// K7: fc5 GEMM [2048,1152] x [256,1152]^T + bias + PReLU -> [2048,256]
// 64x64 tile, BK=16, thread 4x4.
// ---------------------------------------------------------------------------
__global__ __launch_bounds__(256) void k7_fc5(
    const float* __restrict__ W, const float* __restrict__ bias,
    const float* __restrict__ alpha)
{
    __shared__ float As[16][64];
    __shared__ float Bs[16][64];
    const int tid = threadIdx.x;
    const int bm = blockIdx.x, bn = blockIdx.y;
    const int tx = tid & 15, ty = tid >> 4;
    const int lr = tid >> 2;           // 0..63
    const int lq = (tid & 3) * 4;      // 0,4,8,12

    const float* Ab = g_B4 + (size_t)(bm * 64 + lr) * 1152 + lq;
    const float* Wb = W + (size_t)(bn * 64 + lr) * 1152 + lq;

    float acc[4][4];
#pragma unroll
    for (int i = 0; i < 4; i++)
#pragma unroll
        for (int j = 0; j < 4; j++) acc[i][j] = 0.f;

    for (int k0 = 0; k0 < 1152; k0 += 16) {
        float4 av = *(const float4*)(Ab + k0);
        float4 wv = *(const float4*)(Wb + k0);
        As[lq + 0][lr] = av.x; As[lq + 1][lr] = av.y;
        As[lq + 2][lr] = av.z; As[lq + 3][lr] = av.w;
        Bs[lq + 0][lr] = wv.x; Bs[lq + 1][lr] = wv.y;
        Bs[lq + 2][lr] = wv.z; Bs[lq + 3][lr] = wv.w;
        __syncthreads();
#pragma unroll
        for (int k = 0; k < 16; k++) {
            float ar[4], br[4];
#pragma unroll
            for (int i = 0; i < 4; i++) ar[i] = As[k][ty * 4 + i];
#pragma unroll
            for (int j = 0; j < 4; j++) br[j] = Bs[k][tx * 4 + j];
#pragma unroll
            for (int i = 0; i < 4; i++)
#pragma unroll
                for (int j = 0; j < 4; j++) acc[i][j] += ar[i] * br[j];
        }
        __syncthreads();
    }
#pragma unroll
    for (int i = 0; i < 4; i++) {
        const int nn = bm * 64 + ty * 4 + i;
#pragma unroll
        for (int j = 0; j < 4; j++) {
            const int o = bn * 64 + tx * 4 + j;
            float v = acc[i][j] + bias[o];
            v = v >= 0.f ? v : alpha[o] * v;
            g_B5[(size_t)nn * 256 + o] = v;
        }
    }
}

// ---------------------------------------------------------------------------
// K8: heads. One warp per image. out layout: [b: N*4 | c: N*10 | a: N*2]
// ---------------------------------------------------------------------------
__global__ __launch_bounds__(256) void k8_heads(
    const float* __restrict__ w1, const float* __restrict__ b1,
    const float* __restrict__ w2, const float* __restrict__ b2,
    const float* __restrict__ w3, const float* __restrict__ b3,
    float* __restrict__ out)
{
    const int warp = (blockIdx.x * 256 + threadIdx.x) >> 5;
    const int lane = threadIdx.x & 31;
    if (warp >= NIMG) return;
    const float* hv = g_B5 + (size_t)warp * 256;
    float hr[8];
#pragma unroll
    for (int j = 0; j < 8; j++) hr[j] = hv[lane + j * 32];

    auto dot = [&](const float* wrow) {
        float s = 0.f;
#pragma unroll
        for (int j = 0; j < 8; j++) s += hr[j] * wrow[lane + j * 32];
#pragma unroll
        for (int off = 16; off; off >>= 1) s += __shfl_xor_sync(0xffffffffu, s, off);
        return s;
    };

    float* out_b = out;
    float* out_c = out + (size_t)NIMG * 4;
    float* out_a = out + (size_t)NIMG * 14;

    // class probs (softmax over 2)
    float l0 = dot(w1) + b1[0];
    float l1 = dot(w1 + 256) + b1[1];
    float mx = fmaxf(l0, l1);
    float e0 = expf(l0 - mx), e1 = expf(l1 - mx);
    float inv = 1.f / (e0 + e1);
    if (lane == 0) {
        out_a[warp * 2 + 0] = e0 * inv;
        out_a[warp * 2 + 1] = e1 * inv;
    }
    // box regression (4)
#pragma unroll
    for (int o = 0; o < 4; o++) {
        float v = dot(w2 + o * 256) + b2[o];
        if (lane == 0) out_b[warp * 4 + o] = v;
    }
    // landmarks (10)
#pragma unroll
    for (int o = 0; o < 10; o++) {
        float v = dot(w3 + o * 256) + b3[o];
        if (lane == 0) out_c[warp * 10 + o] = v;
    }
}

// ---------------------------------------------------------------------------
extern "C" void kernel_launch(void* const* d_in, const int* in_sizes, int n_in,
                              void* d_out, int out_size)
{
    const float* x    = (const float*)d_in[0];
    const float* c1w  = (const float*)d_in[1];
    const float* c1b  = (const float*)d_in[2];
    const float* a1   = (const float*)d_in[3];
    const float* c2w  = (const float*)d_in[4];
    const float* c2b  = (const float*)d_in[5];
    const float* a2   = (const float*)d_in[6];
    const float* c3w  = (const float*)d_in[7];
    const float* c3b  = (const float*)d_in[8];
    const float* a3   = (const float*)d_in[9];
    const float* c4w  = (const float*)d_in[10];
    const float* c4b  = (const float*)d_in[11];
    const float* a4   = (const float*)d_in[12];
    const float* d5w  = (const float*)d_in[13];
    const float* d5b  = (const float*)d_in[14];
    const float* a5   = (const float*)d_in[15];
    const float* d61w = (const float*)d_in[16];
    const float* d61b = (const float*)d_in[17];
    const float* d62w = (const float*)d_in[18];
    const float* d62b = (const float*)d_in[19];
    const float* d63w = (const float*)d_in[20];
    const float* d63b = (const float*)d_in[21];
    float* out = (float*)d_out;

    // sticky per-function attributes; safe to call every time (ignore errors,
    // first call outside capture already applied them)
    cudaFuncSetAttribute(k2_conv2, cudaFuncAttributeMaxDynamicSharedMemorySize,
                         K2_SMEM_FLOATS * 4);
    cudaFuncSetAttribute(k4_conv3, cudaFuncAttributeMaxDynamicSharedMemorySize,
                         K4_SMEM_FLOATS * 4);
    cudaFuncSetAttribute(k6_conv4, cudaFuncAttributeMaxDynamicSharedMemorySize,
                         K6_SMEM_FLOATS * 4);

    k1_conv1_pool<<<NIMG, 256>>>(x, c1w, c1b, a1);
    k2_conv2<<<NIMG, 256, K2_SMEM_FLOATS * 4>>>(c2w, c2b, a2);
    k3_pool2<<<(NIMG * 64 * 100) / 256, 256>>>();
    k4_conv3<<<NIMG / 4, 256, K4_SMEM_FLOATS * 4>>>(c3w, c3b, a3);
    k5_pool3<<<(NIMG * 64 * 16) / 256, 256>>>();
    k6_conv4<<<NIMG / 16, 256, K6_SMEM_FLOATS * 4>>>(c4w, c4b, a4);
    k7_fc5<<<dim3(NIMG / 64, 256 / 64), 256>>>(d5w, d5b, a5);
    k8_heads<<<(NIMG * 32) / 256, 256>>>(d61w, d61b, d62w, d62b, d63w, d63b, out);
}

// round 2
// speedup vs baseline: 2.4117x; 2.4117x over previous
#include <cuda_runtime.h>
#include <cuda_bf16.h>
#include <math.h>

// ---------------------------------------------------------------------------
// MTCNN ONet forward, N=2048, fp32 direct convolutions (round 2: occupancy).
//  K1a: conv1(3->32,3x3)+PReLU          48x48 -> 46x46   -> g_C1
//  K1b: maxpool(3,2,ceil)               46x46 -> 23x23   -> g_B1
//  K2 : conv2(32->64,3x3)+PReLU         23x23 -> 21x21   -> g_C2   (512 thr)
//  K3 : maxpool(3,2)                    21x21 -> 10x10   -> g_B2
//  K4 : conv3(64->64,3x3)+PReLU         10x10 -> 8x8     -> g_C3   (512 thr, ic-chunked)
//  K5 : maxpool(2,2)                    8x8   -> 4x4     -> g_B3
//  K6 : conv4(64->128,2x2)+PReLU+perm   4x4   -> 1152    -> g_B4
//  K7 : fc5 (1152->256)+PReLU GEMM                        -> g_B5
//  K8 : heads 256->{2 softmax, 4, 10} -> d_out [b|c|a]
// ---------------------------------------------------------------------------

#define NIMG 2048

__device__ float g_C1[(size_t)NIMG * 32 * 46 * 46];  // conv1 out (554MB)
__device__ float g_B1[(size_t)NIMG * 32 * 23 * 23];  // pool1 out
__device__ float g_C2[(size_t)NIMG * 64 * 21 * 21];  // conv2 out
__device__ float g_B2[(size_t)NIMG * 64 * 10 * 10];  // pool2 out
__device__ float g_C3[(size_t)NIMG * 64 * 8 * 8];    // conv3 out
__device__ float g_B3[(size_t)NIMG * 64 * 4 * 4];    // pool3 out
__device__ float g_B4[(size_t)NIMG * 1152];          // conv4 flat
__device__ float g_B5[(size_t)NIMG * 256];           // fc5 out

#define NEG_INF (-1e30f)

// ---------------------------------------------------------------------------
// K1a: conv1 + PReLU only. One image/block, 256 threads, smem ~31KB (high occ).
// Tasks: ocg(4 of 8oc) x y(46) x xg(6 of 8px) = 1104.
// ---------------------------------------------------------------------------
__global__ __launch_bounds__(256) void k1a_conv1(
    const float* __restrict__ x, const float* __restrict__ w,
    const float* __restrict__ bias, const float* __restrict__ alpha)
{
    __shared__ float s_in[3 * 48 * 48];
    __shared__ float s_w[32 * 27];
    __shared__ float s_b[32];
    __shared__ float s_a[32];

    const int n = blockIdx.x;
    {
        const float4* src = (const float4*)(x + (size_t)n * 6912);
        float4* dst = (float4*)s_in;
        for (int i = threadIdx.x; i < 6912 / 4; i += 256) dst[i] = src[i];
        for (int i = threadIdx.x; i < 32 * 27; i += 256) s_w[i] = w[i];
        if (threadIdx.x < 32) {
            s_b[threadIdx.x] = bias[threadIdx.x];
            s_a[threadIdx.x] = alpha[threadIdx.x];
        }
    }
    __syncthreads();

    float* ob = g_C1 + (size_t)n * 32 * 2116;

    for (int t = threadIdx.x; t < 1104; t += 256) {
        const int ocg = t / 276;
        const int rem = t % 276;
        const int y = rem / 6;
        const int xg = (rem % 6) * 8;

        float acc[8][8];
#pragma unroll
        for (int o = 0; o < 8; o++)
#pragma unroll
            for (int j = 0; j < 8; j++) acc[o][j] = 0.f;

#pragma unroll
        for (int ic = 0; ic < 3; ic++) {
#pragma unroll
            for (int ky = 0; ky < 3; ky++) {
                const float* row = s_in + ic * 2304 + (y + ky) * 48;
                float xi[10];
#pragma unroll
                for (int j = 0; j < 10; j++) {
                    int c = xg + j;
                    xi[j] = row[c > 47 ? 47 : c];
                }
#pragma unroll
                for (int o = 0; o < 8; o++) {
                    const float* wp = s_w + (ocg * 8 + o) * 27 + ic * 9 + ky * 3;
                    float w0 = wp[0], w1 = wp[1], w2 = wp[2];
#pragma unroll
                    for (int j = 0; j < 8; j++)
                        acc[o][j] += xi[j] * w0 + xi[j + 1] * w1 + xi[j + 2] * w2;
                }
            }
        }
#pragma unroll
        for (int o = 0; o < 8; o++) {
            const int oc = ocg * 8 + o;
            const float b0 = s_b[oc], al = s_a[oc];
            float* orow = ob + oc * 2116 + y * 46;
#pragma unroll
            for (int j = 0; j < 8; j++) {
                const int xx = xg + j;
                if (xx < 46) {
                    float v = acc[o][j] + b0;
                    orow[xx] = v >= 0.f ? v : al * v;
                }
            }
        }
    }
}

// ---------------------------------------------------------------------------
// K1b: maxpool(3,2,ceil) 46x46 -> 23x23 (clamp duplicates in-window values)
// ---------------------------------------------------------------------------
__global__ __launch_bounds__(256) void k1b_pool1()
{
    const int idx = blockIdx.x * 256 + threadIdx.x;  // exact grid
    const int px = idx % 23;
    const int py = (idx / 23) % 23;
    const int nc = idx / 529;
    const float* base = g_C1 + (size_t)nc * 2116;
    float m = NEG_INF;
#pragma unroll
    for (int ky = 0; ky < 3; ky++) {
        int cy = py * 2 + ky; cy = cy > 45 ? 45 : cy;
#pragma unroll
        for (int kx = 0; kx < 3; kx++) {
            int cx = px * 2 + kx; cx = cx > 45 ? 45 : cx;
            m = fmaxf(m, base[cy * 46 + cx]);
        }
    }
    g_B1[idx] = m;
}

// ---------------------------------------------------------------------------
// K2: conv2 (32->64, 3x3) + PReLU. One image/block, 512 threads (1 round).
// ---------------------------------------------------------------------------
#define K2_SMEM_FLOATS (16928 + 18432 + 64 + 64)
__global__ __launch_bounds__(512, 1) void k2_conv2(
    const float* __restrict__ w, const float* __restrict__ bias,
    const float* __restrict__ alpha)
{
    extern __shared__ float sm2[];
    float* s_in = sm2;              // 32*529
    float* s_w  = sm2 + 16928;      // 64*32*9
    float* s_b  = s_w + 18432;
    float* s_a  = s_b + 64;

    const int n = blockIdx.x;
    {
        const float4* src = (const float4*)(g_B1 + (size_t)n * 16928);
        float4* dst = (float4*)s_in;
        for (int i = threadIdx.x; i < 16928 / 4; i += 512) dst[i] = src[i];
        const float4* ws = (const float4*)w;
        float4* wd = (float4*)s_w;
        for (int i = threadIdx.x; i < 18432 / 4; i += 512) wd[i] = ws[i];
        if (threadIdx.x < 64) {
            s_b[threadIdx.x] = bias[threadIdx.x];
            s_a[threadIdx.x] = alpha[threadIdx.x];
        }
    }
    __syncthreads();

    float* ob = g_C2 + (size_t)n * 64 * 441;

    const int t = threadIdx.x;
    if (t < 504) {
        const int ocg = t / 63;
        const int rem = t % 63;
        const int y = rem / 3;
        const int xg = (rem % 3) * 8;

        float acc[8][8];
#pragma unroll
        for (int o = 0; o < 8; o++)
#pragma unroll
            for (int j = 0; j < 8; j++) acc[o][j] = 0.f;

        for (int ic = 0; ic < 32; ic++) {
#pragma unroll
            for (int ky = 0; ky < 3; ky++) {
                const float* row = s_in + ic * 529 + (y + ky) * 23;
                float xi[10];
#pragma unroll
                for (int j = 0; j < 10; j++) {
                    int c = xg + j;
                    xi[j] = row[c > 22 ? 22 : c];
                }
#pragma unroll
                for (int o = 0; o < 8; o++) {
                    const float* wp = s_w + ((ocg * 8 + o) * 32 + ic) * 9 + ky * 3;
                    float w0 = wp[0], w1 = wp[1], w2 = wp[2];
#pragma unroll
                    for (int j = 0; j < 8; j++)
                        acc[o][j] += xi[j] * w0 + xi[j + 1] * w1 + xi[j + 2] * w2;
                }
            }
        }
#pragma unroll
        for (int o = 0; o < 8; o++) {
            const int oc = ocg * 8 + o;
            const float b0 = s_b[oc], al = s_a[oc];
#pragma unroll
            for (int j = 0; j < 8; j++) {
                const int xx = xg + j;
                if (xx < 21) {
                    float v = acc[o][j] + b0;
                    v = v >= 0.f ? v : al * v;
                    ob[oc * 441 + y * 21 + xx] = v;
                }
            }
        }
    }
}

// ---------------------------------------------------------------------------
// K3: maxpool 3,2 on 21x21 -> 10x10
// ---------------------------------------------------------------------------
__global__ __launch_bounds__(256) void k3_pool2()
{
    const int idx = blockIdx.x * 256 + threadIdx.x;
    const int px = idx % 10;
    const int py = (idx / 10) % 10;
    const int nc = idx / 100;
    const float* base = g_C2 + (size_t)nc * 441;
    float m = NEG_INF;
#pragma unroll
    for (int ky = 0; ky < 3; ky++)
#pragma unroll
        for (int kx = 0; kx < 3; kx++)
            m = fmaxf(m, base[(py * 2 + ky) * 21 + (px * 2 + kx)]);
    g_B2[idx] = m;
}

// ---------------------------------------------------------------------------
// K4: conv3 (64->64, 3x3) + PReLU. 8 images/block, 512 threads.
// Weights all 64 oc resident, chunked over ic (2 halves of 32).
// Thread = (img 0-7, ocg 0-7 of 8oc, y 0-7); accumulators persist across chunks.
// ---------------------------------------------------------------------------
#define K4_SMEM_FLOATS (25600 + 18432 + 64 + 64)
__global__ __launch_bounds__(512, 1) void k4_conv3(
    const float* __restrict__ w, const float* __restrict__ bias,
    const float* __restrict__ alpha)
{
    extern __shared__ float sm4[];
    float* s_in = sm4;             // 8 img * 32 ic * 100
    float* s_w  = sm4 + 25600;     // 64 oc * 32 ic * 9
    float* s_b  = s_w + 18432;
    float* s_a  = s_b + 64;

    const int n0 = blockIdx.x * 8;
    const int t = threadIdx.x;
    const int img = t >> 6;
    const int ocg = (t >> 3) & 7;
    const int y = t & 7;

    if (t < 64) {
        s_b[t] = bias[t];
        s_a[t] = alpha[t];
    }

    float acc[8][8];
#pragma unroll
    for (int o = 0; o < 8; o++)
#pragma unroll
        for (int j = 0; j < 8; j++) acc[o][j] = 0.f;

    for (int chunk = 0; chunk < 2; chunk++) {
        __syncthreads();  // prev compute (and b/a init) done before smem reuse
        {
            // input: per image contiguous 3200 floats (ic-half)
            float4* dst = (float4*)s_in;
            for (int i = t; i < 6400; i += 512) {
                const int im = i / 800, rem = i % 800;
                dst[im * 800 + rem] = ((const float4*)g_B2)[
                    (size_t)(n0 + im) * 1600 + chunk * 800 + rem];
            }
            // weights: [oc][ic 32][9] from [oc][64][9]
            const float4* ws = (const float4*)w;
            float4* wd = (float4*)s_w;
            for (int i = t; i < 4608; i += 512) {
                const int oc = i / 72, rem = i % 72;
                wd[oc * 72 + rem] = ws[oc * 144 + chunk * 72 + rem];
            }
        }
        __syncthreads();

        for (int ic = 0; ic < 32; ic++) {
#pragma unroll
            for (int ky = 0; ky < 3; ky++) {
                const float* row = s_in + img * 3200 + ic * 100 + (y + ky) * 10;
                float xi[10];
#pragma unroll
                for (int j = 0; j < 10; j++) xi[j] = row[j];
#pragma unroll
                for (int o = 0; o < 8; o++) {
                    const float* wp = s_w + (ocg * 8 + o) * 288 + ic * 9 + ky * 3;
                    float w0 = wp[0], w1 = wp[1], w2 = wp[2];
#pragma unroll
                    for (int j = 0; j < 8; j++)
                        acc[o][j] += xi[j] * w0 + xi[j + 1] * w1 + xi[j + 2] * w2;
                }
            }
        }
    }

#pragma unroll
    for (int o = 0; o < 8; o++) {
        const int oc = ocg * 8 + o;
        const float b0 = s_b[oc], al = s_a[oc];
        float* orow = g_C3 + ((size_t)(n0 + img) * 64 + oc) * 64 + y * 8;
#pragma unroll
        for (int j = 0; j < 8; j++) {
            float v = acc[o][j] + b0;
            orow[j] = v >= 0.f ? v : al * v;
        }
    }
}

// ---------------------------------------------------------------------------
// K5: maxpool 2,2 on 8x8 -> 4x4
// ---------------------------------------------------------------------------
__global__ __launch_bounds__(256) void k5_pool3()
{
    const int idx = blockIdx.x * 256 + threadIdx.x;
    const int px = idx % 4;
    const int py = (idx / 4) % 4;
    const int nc = idx / 16;
    const float* base = g_C3 + (size_t)nc * 64;
    float m = fmaxf(fmaxf(base[(py * 2) * 8 + px * 2], base[(py * 2) * 8 + px * 2 + 1]),
                    fmaxf(base[(py * 2 + 1) * 8 + px * 2], base[(py * 2 + 1) * 8 + px * 2 + 1]));
    g_B3[idx] = m;
}

// ---------------------------------------------------------------------------
// K6: conv4 (64->128, 2x2) + PReLU + permute(0,3,2,1) flatten -> [N,1152]
// ---------------------------------------------------------------------------
#define K6_SMEM_FLOATS (16384 + 32768 + 128 + 128)
__global__ __launch_bounds__(256, 1) void k6_conv4(
    const float* __restrict__ w, const float* __restrict__ bias,
    const float* __restrict__ alpha)
{
    extern __shared__ float sm6[];
    float* s_in = sm6;             // 16*64*16
    float* s_w  = sm6 + 16384;     // 128*64*4
    float* s_b  = s_w + 32768;
    float* s_a  = s_b + 128;

    const int n0 = blockIdx.x * 16;
    {
        const float4* src = (const float4*)(g_B3 + (size_t)n0 * 1024);
        float4* dst = (float4*)s_in;
        for (int i = threadIdx.x; i < 16384 / 4; i += 256) dst[i] = src[i];
        const float4* ws = (const float4*)w;
        float4* wd = (float4*)s_w;
        for (int i = threadIdx.x; i < 32768 / 4; i += 256) wd[i] = ws[i];
        if (threadIdx.x < 128) {
            s_b[threadIdx.x] = bias[threadIdx.x];
            s_a[threadIdx.x] = alpha[threadIdx.x];
        }
    }
    __syncthreads();

    for (int t = threadIdx.x; t < 16 * 128; t += 256) {
        const int img = t >> 7;
        const int oc = t & 127;
        float acc[9];
#pragma unroll
        for (int i = 0; i < 9; i++) acc[i] = 0.f;

        for (int ic = 0; ic < 64; ic++) {
            const float* ib = s_in + img * 1024 + ic * 16;
            float xi[16];
#pragma unroll
            for (int i = 0; i < 16; i++) xi[i] = ib[i];
            const float* wp = s_w + (oc * 64 + ic) * 4;
            float w00 = wp[0], w01 = wp[1], w10 = wp[2], w11 = wp[3];
#pragma unroll
            for (int h = 0; h < 3; h++)
#pragma unroll
                for (int ww = 0; ww < 3; ww++)
                    acc[h * 3 + ww] += xi[h * 4 + ww] * w00 + xi[h * 4 + ww + 1] * w01 +
                                       xi[(h + 1) * 4 + ww] * w10 + xi[(h + 1) * 4 + ww + 1] * w11;
        }
        const float b0 = s_b[oc], al = s_a[oc];
        float* ob = g_B4 + (size_t)(n0 + img) * 1152;
#pragma unroll
        for (int h = 0; h < 3; h++)
#pragma unroll
            for (int ww = 0; ww < 3; ww++) {
                float v = acc[h * 3 + ww] + b0;
                v = v >= 0.f ? v : al * v;
                ob[ww * 384 + h * 128 + oc] = v;
            }
    }
}

// ---------------------------------------------------------------------------
// K7: fc5 GEMM [2048,1152] x [256,1152]^T + bias + PReLU -> [2048,256]
// ---------------------------------------------------------------------------
__global__ __launch_bounds__(256) void k7_fc5(
    const float* __restrict__ W, const float* __restrict__ bias,
    const float* __restrict__ alpha)
{
    __shared__ float As[16][64];
    __shared__ float Bs[16][64];
    const int tid = threadIdx.x;
    const int bm = blockIdx.x, bn = blockIdx.y;
    const int tx = tid & 15, ty = tid >> 4;
    const int lr = tid >> 2;
    const int lq = (tid & 3) * 4;

    const float* Ab = g_B4 + (size_t)(bm * 64 + lr) * 1152 + lq;
    const float* Wb = W + (size_t)(bn * 64 + lr) * 1152 + lq;

    float acc[4][4];
#pragma unroll
    for (int i = 0; i < 4; i++)
#pragma unroll
        for (int j = 0; j < 4; j++) acc[i][j] = 0.f;

    for (int k0 = 0; k0 < 1152; k0 += 16) {
        float4 av = *(const float4*)(Ab + k0);
        float4 wv = *(const float4*)(Wb + k0);
        As[lq + 0][lr] = av.x; As[lq + 1][lr] = av.y;
        As[lq + 2][lr] = av.z; As[lq + 3][lr] = av.w;
        Bs[lq + 0][lr] = wv.x; Bs[lq + 1][lr] = wv.y;
        Bs[lq + 2][lr] = wv.z; Bs[lq + 3][lr] = wv.w;
        __syncthreads();
#pragma unroll
        for (int k = 0; k < 16; k++) {
            float ar[4], br[4];
#pragma unroll
            for (int i = 0; i < 4; i++) ar[i] = As[k][ty * 4 + i];
#pragma unroll
            for (int j = 0; j < 4; j++) br[j] = Bs[k][tx * 4 + j];
#pragma unroll
            for (int i = 0; i < 4; i++)
#pragma unroll
                for (int j = 0; j < 4; j++) acc[i][j] += ar[i] * br[j];
        }
        __syncthreads();
    }
#pragma unroll
    for (int i = 0; i < 4; i++) {
        const int nn = bm * 64 + ty * 4 + i;
#pragma unroll
        for (int j = 0; j < 4; j++) {
            const int o = bn * 64 + tx * 4 + j;
            float v = acc[i][j] + bias[o];
            v = v >= 0.f ? v : alpha[o] * v;
            g_B5[(size_t)nn * 256 + o] = v;
        }
    }
}

// ---------------------------------------------------------------------------
// K8: heads. One warp per image. out layout: [b: N*4 | c: N*10 | a: N*2]
// ---------------------------------------------------------------------------
__global__ __launch_bounds__(256) void k8_heads(
    const float* __restrict__ w1, const float* __restrict__ b1,
    const float* __restrict__ w2, const float* __restrict__ b2,
    const float* __restrict__ w3, const float* __restrict__ b3,
    float* __restrict__ out)
{
    const int warp = (blockIdx.x * 256 + threadIdx.x) >> 5;
    const int lane = threadIdx.x & 31;
    if (warp >= NIMG) return;
    const float* hv = g_B5 + (size_t)warp * 256;
    float hr[8];
#pragma unroll
    for (int j = 0; j < 8; j++) hr[j] = hv[lane + j * 32];

    auto dot = [&](const float* wrow) {
        float s = 0.f;
#pragma unroll
        for (int j = 0; j < 8; j++) s += hr[j] * wrow[lane + j * 32];
#pragma unroll
        for (int off = 16; off; off >>= 1) s += __shfl_xor_sync(0xffffffffu, s, off);
        return s;
    };

    float* out_b = out;
    float* out_c = out + (size_t)NIMG * 4;
    float* out_a = out + (size_t)NIMG * 14;

    float l0 = dot(w1) + b1[0];
    float l1 = dot(w1 + 256) + b1[1];
    float mx = fmaxf(l0, l1);
    float e0 = expf(l0 - mx), e1 = expf(l1 - mx);
    float inv = 1.f / (e0 + e1);
    if (lane == 0) {
        out_a[warp * 2 + 0] = e0 * inv;
        out_a[warp * 2 + 1] = e1 * inv;
    }
#pragma unroll
    for (int o = 0; o < 4; o++) {
        float v = dot(w2 + o * 256) + b2[o];
        if (lane == 0) out_b[warp * 4 + o] = v;
    }
#pragma unroll
    for (int o = 0; o < 10; o++) {
        float v = dot(w3 + o * 256) + b3[o];
        if (lane == 0) out_c[warp * 10 + o] = v;
    }
}

// ---------------------------------------------------------------------------
extern "C" void kernel_launch(void* const* d_in, const int* in_sizes, int n_in,
                              void* d_out, int out_size)
{
    const float* x    = (const float*)d_in[0];
    const float* c1w  = (const float*)d_in[1];
    const float* c1b  = (const float*)d_in[2];
    const float* a1   = (const float*)d_in[3];
    const float* c2w  = (const float*)d_in[4];
    const float* c2b  = (const float*)d_in[5];
    const float* a2   = (const float*)d_in[6];
    const float* c3w  = (const float*)d_in[7];
    const float* c3b  = (const float*)d_in[8];
    const float* a3   = (const float*)d_in[9];
    const float* c4w  = (const float*)d_in[10];
    const float* c4b  = (const float*)d_in[11];
    const float* a4   = (const float*)d_in[12];
    const float* d5w  = (const float*)d_in[13];
    const float* d5b  = (const float*)d_in[14];
    const float* a5   = (const float*)d_in[15];
    const float* d61w = (const float*)d_in[16];
    const float* d61b = (const float*)d_in[17];
    const float* d62w = (const float*)d_in[18];
    const float* d62b = (const float*)d_in[19];
    const float* d63w = (const float*)d_in[20];
    const float* d63b = (const float*)d_in[21];
    float* out = (float*)d_out;

    cudaFuncSetAttribute(k2_conv2, cudaFuncAttributeMaxDynamicSharedMemorySize,
                         K2_SMEM_FLOATS * 4);
    cudaFuncSetAttribute(k4_conv3, cudaFuncAttributeMaxDynamicSharedMemorySize,
                         K4_SMEM_FLOATS * 4);
    cudaFuncSetAttribute(k6_conv4, cudaFuncAttributeMaxDynamicSharedMemorySize,
                         K6_SMEM_FLOATS * 4);

    k1a_conv1<<<NIMG, 256>>>(x, c1w, c1b, a1);
    k1b_pool1<<<(NIMG * 32 * 529) / 256, 256>>>();
    k2_conv2<<<NIMG, 512, K2_SMEM_FLOATS * 4>>>(c2w, c2b, a2);
    k3_pool2<<<(NIMG * 64 * 100) / 256, 256>>>();
    k4_conv3<<<NIMG / 8, 512, K4_SMEM_FLOATS * 4>>>(c3w, c3b, a3);
    k5_pool3<<<(NIMG * 64 * 16) / 256, 256>>>();
    k6_conv4<<<NIMG / 16, 256, K6_SMEM_FLOATS * 4>>>(c4w, c4b, a4);
    k7_fc5<<<dim3(NIMG / 64, 256 / 64), 256>>>(d5w, d5b, a5);
    k8_heads<<<(NIMG * 32) / 256, 256>>>(d61w, d61b, d62w, d62b, d63w, d63b, out);
}

// round 3
// speedup vs baseline: 3.0988x; 1.2849x over previous
#include <cuda_runtime.h>
#include <cuda_bf16.h>
#include <math.h>

// ---------------------------------------------------------------------------
// MTCNN ONet forward, N=2048, fp32, fully fused pools (round 3).
//  K1: conv1(3->32)+PReLU+maxpool(3,2,ceil) 48x48 -> 23x23  -> g_B1
//      block = (image, ocg of 8), conv kept in smem, pool in-block
//  K2: conv2(32->64)+PReLU+maxpool(3,2)     23x23 -> 10x10  -> g_B2
//      block = image, conv stored to smem overlay, pool in-block
//  K4: conv3(64->64)+PReLU+maxpool(2,2)     10x10 -> 4x4    -> g_B3
//      8 images/block, pool via shfl_xor row pairing
//  K6: conv4(64->128)+PReLU+permute flatten 4x4 -> 1152     -> g_B4
//  K7: fc5 (1152->256)+PReLU GEMM                            -> g_B5
//  K8: heads 256->{2 softmax, 4, 10} -> d_out [b|c|a]
// ---------------------------------------------------------------------------

#define NIMG 2048

__device__ float g_B1[(size_t)NIMG * 32 * 23 * 23];  // pool1 out
__device__ float g_B2[(size_t)NIMG * 64 * 10 * 10];  // pool2 out
__device__ float g_B3[(size_t)NIMG * 64 * 4 * 4];    // pool3 out
__device__ float g_B4[(size_t)NIMG * 1152];          // conv4 flat
__device__ float g_B5[(size_t)NIMG * 256];           // fc5 out

#define NEG_INF (-1e30f)

// ---------------------------------------------------------------------------
// K1: conv1 + PReLU + pool1 fused. Grid (NIMG, 4), 256 threads.
// smem: input 27KB + conv buf (8oc x 46x46) 67.7KB + weights ~1KB = ~96KB
// ---------------------------------------------------------------------------
#define K1_SMEM_FLOATS (6912 + 16928 + 216 + 8 + 8)
__global__ __launch_bounds__(256, 2) void k1_conv1_pool(
    const float* __restrict__ x, const float* __restrict__ w,
    const float* __restrict__ bias, const float* __restrict__ alpha)
{
    extern __shared__ float sm1[];
    float* s_in = sm1;            // 3*48*48
    float* s_cv = sm1 + 6912;     // 8*46*46
    float* s_w  = s_cv + 16928;   // 8*27
    float* s_b  = s_w + 216;      // 8
    float* s_a  = s_b + 8;        // 8

    const int n = blockIdx.x;
    const int ocg = blockIdx.y;   // 0..3, handles oc ocg*8..ocg*8+7
    const int tid = threadIdx.x;
    {
        const float4* src = (const float4*)(x + (size_t)n * 6912);
        float4* dst = (float4*)s_in;
        for (int i = tid; i < 6912 / 4; i += 256) dst[i] = src[i];
        if (tid < 216) s_w[tid] = w[ocg * 216 + tid];
        if (tid < 8) {
            s_b[tid] = bias[ocg * 8 + tid];
            s_a[tid] = alpha[ocg * 8 + tid];
        }
    }
    __syncthreads();

    // conv: tasks (y 0..45, xg 0..5 of 8 px) = 276
    for (int t = tid; t < 276; t += 256) {
        const int y = t / 6;
        const int xg = (t % 6) * 8;

        float acc[8][8];
#pragma unroll
        for (int o = 0; o < 8; o++)
#pragma unroll
            for (int j = 0; j < 8; j++) acc[o][j] = 0.f;

#pragma unroll
        for (int ic = 0; ic < 3; ic++) {
#pragma unroll
            for (int ky = 0; ky < 3; ky++) {
                const float* row = s_in + ic * 2304 + (y + ky) * 48;
                float xi[10];
#pragma unroll
                for (int j = 0; j < 10; j++) {
                    int c = xg + j;
                    xi[j] = row[c > 47 ? 47 : c];
                }
#pragma unroll
                for (int o = 0; o < 8; o++) {
                    const float* wp = s_w + o * 27 + ic * 9 + ky * 3;
                    float w0 = wp[0], w1 = wp[1], w2 = wp[2];
#pragma unroll
                    for (int j = 0; j < 8; j++)
                        acc[o][j] += xi[j] * w0 + xi[j + 1] * w1 + xi[j + 2] * w2;
                }
            }
        }
#pragma unroll
        for (int o = 0; o < 8; o++) {
            const float b0 = s_b[o], al = s_a[o];
            float* orow = s_cv + o * 2116 + y * 46;
#pragma unroll
            for (int j = 0; j < 8; j++) {
                const int xx = xg + j;
                if (xx < 46) {
                    float v = acc[o][j] + b0;
                    orow[xx] = v >= 0.f ? v : al * v;
                }
            }
        }
    }
    __syncthreads();

    // pool(3,2,ceil): 46 -> 23, clamp edge (duplicates in-window values)
    float* ob = g_B1 + ((size_t)n * 32 + ocg * 8) * 529;
    for (int i = tid; i < 8 * 529; i += 256) {
        const int o = i / 529;
        const int rem = i % 529;
        const int py = rem / 23;
        const int px = rem % 23;
        const float* base = s_cv + o * 2116;
        float m = NEG_INF;
#pragma unroll
        for (int ky = 0; ky < 3; ky++) {
            int cy = py * 2 + ky; cy = cy > 45 ? 45 : cy;
#pragma unroll
            for (int kx = 0; kx < 3; kx++) {
                int cx = px * 2 + kx; cx = cx > 45 ? 45 : cx;
                m = fmaxf(m, base[cy * 46 + cx]);
            }
        }
        ob[i] = m;
    }
}

// ---------------------------------------------------------------------------
// K2: conv2 + PReLU + pool2 fused. One image/block, 512 threads.
// After compute, conv output (64*441 = 28224 floats) overlays the dead
// input+weight smem region (35360 floats); bias/alpha live above it.
// ---------------------------------------------------------------------------
#define K2_SMEM_FLOATS (16928 + 18432 + 64 + 64)
__global__ __launch_bounds__(512, 1) void k2_conv2_pool(
    const float* __restrict__ w, const float* __restrict__ bias,
    const float* __restrict__ alpha)
{
    extern __shared__ float sm2[];
    float* s_in = sm2;              // 32*529
    float* s_w  = sm2 + 16928;      // 64*32*9
    float* s_b  = s_w + 18432;      // 64   (offset 35360, above overlay)
    float* s_a  = s_b + 64;
    float* s_cv = sm2;              // overlay: 64*441 = 28224 < 35360

    const int n = blockIdx.x;
    const int t = threadIdx.x;
    {
        const float4* src = (const float4*)(g_B1 + (size_t)n * 16928);
        float4* dst = (float4*)s_in;
        for (int i = t; i < 16928 / 4; i += 512) dst[i] = src[i];
        const float4* ws = (const float4*)w;
        float4* wd = (float4*)s_w;
        for (int i = t; i < 18432 / 4; i += 512) wd[i] = ws[i];
        if (t < 64) {
            s_b[t] = bias[t];
            s_a[t] = alpha[t];
        }
    }
    __syncthreads();

    // compute into registers
    float acc[8][8];
    int ocg = 0, y = 0, xg = 0;
    const bool active = (t < 504);
    if (active) {
        ocg = t / 63;
        const int rem = t % 63;
        y = rem / 3;
        xg = (rem % 3) * 8;
#pragma unroll
        for (int o = 0; o < 8; o++)
#pragma unroll
            for (int j = 0; j < 8; j++) acc[o][j] = 0.f;

        for (int ic = 0; ic < 32; ic++) {
#pragma unroll
            for (int ky = 0; ky < 3; ky++) {
                const float* row = s_in + ic * 529 + (y + ky) * 23;
                float xi[10];
#pragma unroll
                for (int j = 0; j < 10; j++) {
                    int c = xg + j;
                    xi[j] = row[c > 22 ? 22 : c];
                }
#pragma unroll
                for (int o = 0; o < 8; o++) {
                    const float* wp = s_w + ((ocg * 8 + o) * 32 + ic) * 9 + ky * 3;
                    float w0 = wp[0], w1 = wp[1], w2 = wp[2];
#pragma unroll
                    for (int j = 0; j < 8; j++)
                        acc[o][j] += xi[j] * w0 + xi[j + 1] * w1 + xi[j + 2] * w2;
                }
            }
        }
    }
    __syncthreads();   // all reads of s_in / s_w complete

    // store conv+PReLU into smem overlay
    if (active) {
#pragma unroll
        for (int o = 0; o < 8; o++) {
            const int oc = ocg * 8 + o;
            const float b0 = s_b[oc], al = s_a[oc];
#pragma unroll
            for (int j = 0; j < 8; j++) {
                const int xx = xg + j;
                if (xx < 21) {
                    float v = acc[o][j] + b0;
                    s_cv[oc * 441 + y * 21 + xx] = v >= 0.f ? v : al * v;
                }
            }
        }
    }
    __syncthreads();

    // pool(3,2): 21 -> 10 (exact), write g_B2 [n][64][10][10]
    float* ob = g_B2 + (size_t)n * 6400;
    for (int i = t; i < 6400; i += 512) {
        const int oc = i / 100;
        const int rem = i % 100;
        const int py = rem / 10;
        const int px = rem % 10;
        const float* base = s_cv + oc * 441 + (py * 2) * 21 + px * 2;
        float m = NEG_INF;
#pragma unroll
        for (int ky = 0; ky < 3; ky++)
#pragma unroll
            for (int kx = 0; kx < 3; kx++)
                m = fmaxf(m, base[ky * 21 + kx]);
        ob[i] = m;
    }
}

// ---------------------------------------------------------------------------
// K4: conv3 + PReLU + pool3(2,2) fused. 8 images/block, 512 threads.
// Thread = (img, ocg of 8oc, y). Pool rows paired via shfl_xor(1) (y bit 0
// is lane bit 0); even-y lanes write pooled float4 per oc.
// ---------------------------------------------------------------------------
#define K4_SMEM_FLOATS (25600 + 18432 + 64 + 64)
__global__ __launch_bounds__(512, 1) void k4_conv3_pool(
    const float* __restrict__ w, const float* __restrict__ bias,
    const float* __restrict__ alpha)
{
    extern __shared__ float sm4[];
    float* s_in = sm4;             // 8 img * 32 ic * 100
    float* s_w  = sm4 + 25600;     // 64 oc * 32 ic * 9
    float* s_b  = s_w + 18432;
    float* s_a  = s_b + 64;

    const int n0 = blockIdx.x * 8;
    const int t = threadIdx.x;
    const int img = t >> 6;
    const int ocg = (t >> 3) & 7;
    const int y = t & 7;

    if (t < 64) {
        s_b[t] = bias[t];
        s_a[t] = alpha[t];
    }

    float acc[8][8];
#pragma unroll
    for (int o = 0; o < 8; o++)
#pragma unroll
        for (int j = 0; j < 8; j++) acc[o][j] = 0.f;

    for (int chunk = 0; chunk < 2; chunk++) {
        __syncthreads();
        {
            float4* dst = (float4*)s_in;
            for (int i = t; i < 6400; i += 512) {
                const int im = i / 800, rem = i % 800;
                dst[im * 800 + rem] = ((const float4*)g_B2)[
                    (size_t)(n0 + im) * 1600 + chunk * 800 + rem];
            }
            const float4* ws = (const float4*)w;
            float4* wd = (float4*)s_w;
            for (int i = t; i < 4608; i += 512) {
                const int oc = i / 72, rem = i % 72;
                wd[oc * 72 + rem] = ws[oc * 144 + chunk * 72 + rem];
            }
        }
        __syncthreads();

        for (int ic = 0; ic < 32; ic++) {
#pragma unroll
            for (int ky = 0; ky < 3; ky++) {
                const float* row = s_in + img * 3200 + ic * 100 + (y + ky) * 10;
                float xi[10];
#pragma unroll
                for (int j = 0; j < 10; j++) xi[j] = row[j];
#pragma unroll
                for (int o = 0; o < 8; o++) {
                    const float* wp = s_w + (ocg * 8 + o) * 288 + ic * 9 + ky * 3;
                    float w0 = wp[0], w1 = wp[1], w2 = wp[2];
#pragma unroll
                    for (int j = 0; j < 8; j++)
                        acc[o][j] += xi[j] * w0 + xi[j + 1] * w1 + xi[j + 2] * w2;
                }
            }
        }
    }

    // PReLU + pool 2x2: vertical pair via shfl_xor(1), horizontal in-thread.
    const int y2 = y >> 1;
#pragma unroll
    for (int o = 0; o < 8; o++) {
        const int oc = ocg * 8 + o;
        const float b0 = s_b[oc], al = s_a[oc];
        float v[8];
#pragma unroll
        for (int j = 0; j < 8; j++) {
            float u = acc[o][j] + b0;
            v[j] = u >= 0.f ? u : al * u;
        }
        float m[8];
#pragma unroll
        for (int j = 0; j < 8; j++)
            m[j] = fmaxf(v[j], __shfl_xor_sync(0xffffffffu, v[j], 1));
        if ((y & 1) == 0) {
            float4 p;
            p.x = fmaxf(m[0], m[1]);
            p.y = fmaxf(m[2], m[3]);
            p.z = fmaxf(m[4], m[5]);
            p.w = fmaxf(m[6], m[7]);
            *(float4*)(g_B3 + ((size_t)(n0 + img) * 64 + oc) * 16 + y2 * 4) = p;
        }
    }
}

// ---------------------------------------------------------------------------
// K6: conv4 (64->128, 2x2) + PReLU + permute(0,3,2,1) flatten -> [N,1152]
// ---------------------------------------------------------------------------
#define K6_SMEM_FLOATS (16384 + 32768 + 128 + 128)
__global__ __launch_bounds__(256, 1) void k6_conv4(
    const float* __restrict__ w, const float* __restrict__ bias,
    const float* __restrict__ alpha)
{
    extern __shared__ float sm6[];
    float* s_in = sm6;             // 16*64*16
    float* s_w  = sm6 + 16384;     // 128*64*4
    float* s_b  = s_w + 32768;
    float* s_a  = s_b + 128;

    const int n0 = blockIdx.x * 16;
    {
        const float4* src = (const float4*)(g_B3 + (size_t)n0 * 1024);
        float4* dst = (float4*)s_in;
        for (int i = threadIdx.x; i < 16384 / 4; i += 256) dst[i] = src[i];
        const float4* ws = (const float4*)w;
        float4* wd = (float4*)s_w;
        for (int i = threadIdx.x; i < 32768 / 4; i += 256) wd[i] = ws[i];
        if (threadIdx.x < 128) {
            s_b[threadIdx.x] = bias[threadIdx.x];
            s_a[threadIdx.x] = alpha[threadIdx.x];
        }
    }
    __syncthreads();

    for (int t = threadIdx.x; t < 16 * 128; t += 256) {
        const int img = t >> 7;
        const int oc = t & 127;
        float acc[9];
#pragma unroll
        for (int i = 0; i < 9; i++) acc[i] = 0.f;

        for (int ic = 0; ic < 64; ic++) {
            const float* ib = s_in + img * 1024 + ic * 16;
            float xi[16];
#pragma unroll
            for (int i = 0; i < 16; i++) xi[i] = ib[i];
            const float* wp = s_w + (oc * 64 + ic) * 4;
            float w00 = wp[0], w01 = wp[1], w10 = wp[2], w11 = wp[3];
#pragma unroll
            for (int h = 0; h < 3; h++)
#pragma unroll
                for (int ww = 0; ww < 3; ww++)
                    acc[h * 3 + ww] += xi[h * 4 + ww] * w00 + xi[h * 4 + ww + 1] * w01 +
                                       xi[(h + 1) * 4 + ww] * w10 + xi[(h + 1) * 4 + ww + 1] * w11;
        }
        const float b0 = s_b[oc], al = s_a[oc];
        float* ob = g_B4 + (size_t)(n0 + img) * 1152;
#pragma unroll
        for (int h = 0; h < 3; h++)
#pragma unroll
            for (int ww = 0; ww < 3; ww++) {
                float v = acc[h * 3 + ww] + b0;
                v = v >= 0.f ? v : al * v;
                ob[ww * 384 + h * 128 + oc] = v;
            }
    }
}

// ---------------------------------------------------------------------------
// K7: fc5 GEMM [2048,1152] x [256,1152]^T + bias + PReLU -> [2048,256]
// ---------------------------------------------------------------------------
__global__ __launch_bounds__(256) void k7_fc5(
    const float* __restrict__ W, const float* __restrict__ bias,
    const float* __restrict__ alpha)
{
    __shared__ float As[16][64];
    __shared__ float Bs[16][64];
    const int tid = threadIdx.x;
    const int bm = blockIdx.x, bn = blockIdx.y;
    const int tx = tid & 15, ty = tid >> 4;
    const int lr = tid >> 2;
    const int lq = (tid & 3) * 4;

    const float* Ab = g_B4 + (size_t)(bm * 64 + lr) * 1152 + lq;
    const float* Wb = W + (size_t)(bn * 64 + lr) * 1152 + lq;

    float acc[4][4];
#pragma unroll
    for (int i = 0; i < 4; i++)
#pragma unroll
        for (int j = 0; j < 4; j++) acc[i][j] = 0.f;

    for (int k0 = 0; k0 < 1152; k0 += 16) {
        float4 av = *(const float4*)(Ab + k0);
        float4 wv = *(const float4*)(Wb + k0);
        As[lq + 0][lr] = av.x; As[lq + 1][lr] = av.y;
        As[lq + 2][lr] = av.z; As[lq + 3][lr] = av.w;
        Bs[lq + 0][lr] = wv.x; Bs[lq + 1][lr] = wv.y;
        Bs[lq + 2][lr] = wv.z; Bs[lq + 3][lr] = wv.w;
        __syncthreads();
#pragma unroll
        for (int k = 0; k < 16; k++) {
            float ar[4], br[4];
#pragma unroll
            for (int i = 0; i < 4; i++) ar[i] = As[k][ty * 4 + i];
#pragma unroll
            for (int j = 0; j < 4; j++) br[j] = Bs[k][tx * 4 + j];
#pragma unroll
            for (int i = 0; i < 4; i++)
#pragma unroll
                for (int j = 0; j < 4; j++) acc[i][j] += ar[i] * br[j];
        }
        __syncthreads();
    }
#pragma unroll
    for (int i = 0; i < 4; i++) {
        const int nn = bm * 64 + ty * 4 + i;
#pragma unroll
        for (int j = 0; j < 4; j++) {
            const int o = bn * 64 + tx * 4 + j;
            float v = acc[i][j] + bias[o];
            v = v >= 0.f ? v : alpha[o] * v;
            g_B5[(size_t)nn * 256 + o] = v;
        }
    }
}

// ---------------------------------------------------------------------------
// K8: heads. One warp per image. out layout: [b: N*4 | c: N*10 | a: N*2]
// ---------------------------------------------------------------------------
__global__ __launch_bounds__(256) void k8_heads(
    const float* __restrict__ w1, const float* __restrict__ b1,
    const float* __restrict__ w2, const float* __restrict__ b2,
    const float* __restrict__ w3, const float* __restrict__ b3,
    float* __restrict__ out)
{
    const int warp = (blockIdx.x * 256 + threadIdx.x) >> 5;
    const int lane = threadIdx.x & 31;
    if (warp >= NIMG) return;
    const float* hv = g_B5 + (size_t)warp * 256;
    float hr[8];
#pragma unroll
    for (int j = 0; j < 8; j++) hr[j] = hv[lane + j * 32];

    auto dot = [&](const float* wrow) {
        float s = 0.f;
#pragma unroll
        for (int j = 0; j < 8; j++) s += hr[j] * wrow[lane + j * 32];
#pragma unroll
        for (int off = 16; off; off >>= 1) s += __shfl_xor_sync(0xffffffffu, s, off);
        return s;
    };

    float* out_b = out;
    float* out_c = out + (size_t)NIMG * 4;
    float* out_a = out + (size_t)NIMG * 14;

    float l0 = dot(w1) + b1[0];
    float l1 = dot(w1 + 256) + b1[1];
    float mx = fmaxf(l0, l1);
    float e0 = expf(l0 - mx), e1 = expf(l1 - mx);
    float inv = 1.f / (e0 + e1);
    if (lane == 0) {
        out_a[warp * 2 + 0] = e0 * inv;
        out_a[warp * 2 + 1] = e1 * inv;
    }
#pragma unroll
    for (int o = 0; o < 4; o++) {
        float v = dot(w2 + o * 256) + b2[o];
        if (lane == 0) out_b[warp * 4 + o] = v;
    }
#pragma unroll
    for (int o = 0; o < 10; o++) {
        float v = dot(w3 + o * 256) + b3[o];
        if (lane == 0) out_c[warp * 10 + o] = v;
    }
}

// ---------------------------------------------------------------------------
extern "C" void kernel_launch(void* const* d_in, const int* in_sizes, int n_in,
                              void* d_out, int out_size)
{
    const float* x    = (const float*)d_in[0];
    const float* c1w  = (const float*)d_in[1];
    const float* c1b  = (const float*)d_in[2];
    const float* a1   = (const float*)d_in[3];
    const float* c2w  = (const float*)d_in[4];
    const float* c2b  = (const float*)d_in[5];
    const float* a2   = (const float*)d_in[6];
    const float* c3w  = (const float*)d_in[7];
    const float* c3b  = (const float*)d_in[8];
    const float* a3   = (const float*)d_in[9];
    const float* c4w  = (const float*)d_in[10];
    const float* c4b  = (const float*)d_in[11];
    const float* a4   = (const float*)d_in[12];
    const float* d5w  = (const float*)d_in[13];
    const float* d5b  = (const float*)d_in[14];
    const float* a5   = (const float*)d_in[15];
    const float* d61w = (const float*)d_in[16];
    const float* d61b = (const float*)d_in[17];
    const float* d62w = (const float*)d_in[18];
    const float* d62b = (const float*)d_in[19];
    const float* d63w = (const float*)d_in[20];
    const float* d63b = (const float*)d_in[21];
    float* out = (float*)d_out;

    cudaFuncSetAttribute(k1_conv1_pool, cudaFuncAttributeMaxDynamicSharedMemorySize,
                         K1_SMEM_FLOATS * 4);
    cudaFuncSetAttribute(k2_conv2_pool, cudaFuncAttributeMaxDynamicSharedMemorySize,
                         K2_SMEM_FLOATS * 4);
    cudaFuncSetAttribute(k4_conv3_pool, cudaFuncAttributeMaxDynamicSharedMemorySize,
                         K4_SMEM_FLOATS * 4);
    cudaFuncSetAttribute(k6_conv4, cudaFuncAttributeMaxDynamicSharedMemorySize,
                         K6_SMEM_FLOATS * 4);

    k1_conv1_pool<<<dim3(NIMG, 4), 256, K1_SMEM_FLOATS * 4>>>(x, c1w, c1b, a1);
    k2_conv2_pool<<<NIMG, 512, K2_SMEM_FLOATS * 4>>>(c2w, c2b, a2);
    k4_conv3_pool<<<NIMG / 8, 512, K4_SMEM_FLOATS * 4>>>(c3w, c3b, a3);
    k6_conv4<<<NIMG / 16, 256, K6_SMEM_FLOATS * 4>>>(c4w, c4b, a4);
    k7_fc5<<<dim3(NIMG / 64, 256 / 64), 256>>>(d5w, d5b, a5);
    k8_heads<<<(NIMG * 32) / 256, 256>>>(d61w, d61b, d62w, d62b, d63w, d63b, out);
}

// round 4
// speedup vs baseline: 3.3106x; 1.0683x over previous
#include <cuda_runtime.h>
#include <cuda_bf16.h>
#include <math.h>

// ---------------------------------------------------------------------------
// MTCNN ONet forward, N=2048, fp32, fused pools, occupancy-tuned (round 4).
//  K1: conv1+PReLU+pool(3,2,ceil)  48->23   grid(2048,4) x288   -> g_B1
//  K2: conv2+PReLU+pool(3,2)       23->10   grid(2048,2) x256   -> g_B2
//      oc-half per block, 2 CTAs/SM, vectorized transposed weights
//  K4: conv3+PReLU+pool(2,2)       10->4    grid 512 x256       -> g_B3
//      4 img/block, 16-ic weight chunks, 2 CTAs/SM
//  K6: conv4+PReLU+permute flatten 4x4->1152 grid(256,2) x256   -> g_B4
//  K7: fc5 GEMM+PReLU (ping-pong)                               -> g_B5
//  K8: heads -> d_out [b|c|a]
// ---------------------------------------------------------------------------

#define NIMG 2048

__device__ float g_B1[(size_t)NIMG * 32 * 23 * 23];
__device__ float g_B2[(size_t)NIMG * 64 * 10 * 10];
__device__ float g_B3[(size_t)NIMG * 64 * 4 * 4];
__device__ float g_B4[(size_t)NIMG * 1152];
__device__ float g_B5[(size_t)NIMG * 256];

#define NEG_INF (-1e30f)

// ---------------------------------------------------------------------------
// K1: conv1 + PReLU + pool1. Grid (NIMG, 4), 288 threads, 2 CTAs/SM.
// ---------------------------------------------------------------------------
#define K1_SMEM_FLOATS (6912 + 16928 + 216 + 8 + 8)
__global__ __launch_bounds__(288, 2) void k1_conv1_pool(
    const float* __restrict__ x, const float* __restrict__ w,
    const float* __restrict__ bias, const float* __restrict__ alpha)
{
    extern __shared__ float sm1[];
    float* s_in = sm1;            // 3*48*48
    float* s_cv = sm1 + 6912;     // 8*46*46
    float* s_w  = s_cv + 16928;   // 8*27
    float* s_b  = s_w + 216;
    float* s_a  = s_b + 8;

    const int n = blockIdx.x;
    const int ocg = blockIdx.y;
    const int tid = threadIdx.x;
    {
        const float4* src = (const float4*)(x + (size_t)n * 6912);
        float4* dst = (float4*)s_in;
        for (int i = tid; i < 6912 / 4; i += 288) dst[i] = src[i];
        if (tid < 216) s_w[tid] = w[ocg * 216 + tid];
        if (tid < 8) {
            s_b[tid] = bias[ocg * 8 + tid];
            s_a[tid] = alpha[ocg * 8 + tid];
        }
    }
    __syncthreads();

    if (tid < 276) {
        const int y = tid / 6;
        const int xg = (tid % 6) * 8;

        float acc[8][8];
#pragma unroll
        for (int o = 0; o < 8; o++)
#pragma unroll
            for (int j = 0; j < 8; j++) acc[o][j] = 0.f;

#pragma unroll
        for (int ic = 0; ic < 3; ic++) {
#pragma unroll
            for (int ky = 0; ky < 3; ky++) {
                const float* row = s_in + ic * 2304 + (y + ky) * 48;
                float xi[10];
#pragma unroll
                for (int j = 0; j < 10; j++) {
                    int c = xg + j;
                    xi[j] = row[c > 47 ? 47 : c];
                }
#pragma unroll
                for (int o = 0; o < 8; o++) {
                    const float* wp = s_w + o * 27 + ic * 9 + ky * 3;
                    float w0 = wp[0], w1 = wp[1], w2 = wp[2];
#pragma unroll
                    for (int j = 0; j < 8; j++)
                        acc[o][j] += xi[j] * w0 + xi[j + 1] * w1 + xi[j + 2] * w2;
                }
            }
        }
#pragma unroll
        for (int o = 0; o < 8; o++) {
            const float b0 = s_b[o], al = s_a[o];
            float* orow = s_cv + o * 2116 + y * 46;
#pragma unroll
            for (int j = 0; j < 8; j++) {
                const int xx = xg + j;
                if (xx < 46) {
                    float v = acc[o][j] + b0;
                    orow[xx] = v >= 0.f ? v : al * v;
                }
            }
        }
    }
    __syncthreads();

    float* ob = g_B1 + ((size_t)n * 32 + ocg * 8) * 529;
    for (int i = tid; i < 8 * 529; i += 288) {
        const int o = i / 529;
        const int rem = i % 529;
        const int py = rem / 23;
        const int px = rem % 23;
        const float* base = s_cv + o * 2116;
        float m = NEG_INF;
#pragma unroll
        for (int ky = 0; ky < 3; ky++) {
            int cy = py * 2 + ky; cy = cy > 45 ? 45 : cy;
#pragma unroll
            for (int kx = 0; kx < 3; kx++) {
                int cx = px * 2 + kx; cx = cx > 45 ? 45 : cx;
                m = fmaxf(m, base[cy * 46 + cx]);
            }
        }
        ob[i] = m;
    }
}

// ---------------------------------------------------------------------------
// K2: conv2 + PReLU + pool2. Grid (NIMG, 2): block = (image, oc-half of 32).
// smem 105KB -> 2 CTAs/SM. Weights transposed to [rk=ic*9+ky*3+kx][oc 32]
// for float4 reads in the microkernel.
// ---------------------------------------------------------------------------
#define K2_SMEM_FLOATS (16928 + 9216 + 32 + 32)
__global__ __launch_bounds__(256, 2) void k2_conv2_pool(
    const float* __restrict__ w, const float* __restrict__ bias,
    const float* __restrict__ alpha)
{
    extern __shared__ float sm2[];
    float* s_in = sm2;              // 32*529
    float* s_w  = sm2 + 16928;      // [288][32]
    float* s_b  = s_w + 9216;       // 32
    float* s_a  = s_b + 32;
    float* s_cv = sm2;              // overlay: 32*441 = 14112 < 16928

    const int n = blockIdx.x;
    const int ocq = blockIdx.y;     // oc half
    const int t = threadIdx.x;

    // stage raw weights (padded rows 289) in s_in region, then transpose
    {
        const float* wsrc = w + (size_t)ocq * 9216;
        for (int i = t; i < 9216; i += 256) {
            const int oc = i / 288, r = i - oc * 288;
            s_in[oc * 289 + r] = wsrc[i];
        }
    }
    __syncthreads();
    for (int i = t; i < 9216; i += 256) {
        const int r = i >> 5, oc = i & 31;
        s_w[i] = s_in[oc * 289 + r];
    }
    __syncthreads();
    {
        const float4* src = (const float4*)(g_B1 + (size_t)n * 16928);
        float4* dst = (float4*)s_in;
        for (int i = t; i < 4232; i += 256) dst[i] = src[i];
        if (t < 32) {
            s_b[t] = bias[ocq * 32 + t];
            s_a[t] = alpha[ocq * 32 + t];
        }
    }
    __syncthreads();

    float acc[8][8];
    int ocg = 0, y = 0, xg = 0;
    const bool active = (t < 252);
    if (active) {
        ocg = t / 63;                 // 0..3 (8 oc each)
        const int rem = t % 63;
        y = rem / 3;
        xg = (rem % 3) * 8;
#pragma unroll
        for (int o = 0; o < 8; o++)
#pragma unroll
            for (int j = 0; j < 8; j++) acc[o][j] = 0.f;

        for (int ic = 0; ic < 32; ic++) {
#pragma unroll
            for (int ky = 0; ky < 3; ky++) {
                const float* row = s_in + ic * 529 + (y + ky) * 23;
                float xi[10];
#pragma unroll
                for (int j = 0; j < 10; j++) {
                    int c = xg + j;
                    xi[j] = row[c > 22 ? 22 : c];
                }
                const float* wb = s_w + (ic * 9 + ky * 3) * 32 + ocg * 8;
#pragma unroll
                for (int kx = 0; kx < 3; kx++) {
                    float4 wa = *(const float4*)(wb + kx * 32);
                    float4 wc = *(const float4*)(wb + kx * 32 + 4);
                    float wo[8] = {wa.x, wa.y, wa.z, wa.w, wc.x, wc.y, wc.z, wc.w};
#pragma unroll
                    for (int o = 0; o < 8; o++)
#pragma unroll
                        for (int j = 0; j < 8; j++)
                            acc[o][j] += xi[j + kx] * wo[o];
                }
            }
        }
    }
    __syncthreads();   // all reads of s_in / s_w done

    if (active) {
#pragma unroll
        for (int o = 0; o < 8; o++) {
            const int ocl = ocg * 8 + o;
            const float b0 = s_b[ocl], al = s_a[ocl];
#pragma unroll
            for (int j = 0; j < 8; j++) {
                const int xx = xg + j;
                if (xx < 21) {
                    float v = acc[o][j] + b0;
                    s_cv[ocl * 441 + y * 21 + xx] = v >= 0.f ? v : al * v;
                }
            }
        }
    }
    __syncthreads();

    float* ob = g_B2 + (size_t)n * 6400 + (size_t)ocq * 3200;
    for (int i = t; i < 3200; i += 256) {
        const int ocl = i / 100;
        const int rem = i % 100;
        const int py = rem / 10;
        const int px = rem % 10;
        const float* base = s_cv + ocl * 441 + (py * 2) * 21 + px * 2;
        float m = NEG_INF;
#pragma unroll
        for (int ky = 0; ky < 3; ky++)
#pragma unroll
            for (int kx = 0; kx < 3; kx++)
                m = fmaxf(m, base[ky * 21 + kx]);
        ob[i] = m;
    }
}

// ---------------------------------------------------------------------------
// K4: conv3 + PReLU + pool3(2,2). 4 img/block, 256 thr, grid 512.
// Weights chunked over ic (4 chunks of 16); smem 63KB -> 2 CTAs/SM.
// ---------------------------------------------------------------------------
#define K4_SMEM_FLOATS (6400 + 9216 + 64 + 64)
__global__ __launch_bounds__(256) void k4_conv3_pool(
    const float* __restrict__ w, const float* __restrict__ bias,
    const float* __restrict__ alpha)
{
    extern __shared__ float sm4[];
    float* s_in = sm4;             // 4 img * 16 ic * 100
    float* s_w  = sm4 + 6400;      // 64 oc * 16 ic * 9
    float* s_b  = s_w + 9216;
    float* s_a  = s_b + 64;

    const int n0 = blockIdx.x * 4;
    const int t = threadIdx.x;
    const int img = t >> 6;
    const int ocg = (t >> 3) & 7;
    const int y = t & 7;

    if (t < 64) {
        s_b[t] = bias[t];
        s_a[t] = alpha[t];
    }

    float acc[8][8];
#pragma unroll
    for (int o = 0; o < 8; o++)
#pragma unroll
        for (int j = 0; j < 8; j++) acc[o][j] = 0.f;

    for (int chunk = 0; chunk < 4; chunk++) {
        __syncthreads();
        {
            float4* dst = (float4*)s_in;
            for (int i = t; i < 1600; i += 256) {
                const int im = i / 400, rem = i % 400;
                dst[i] = ((const float4*)g_B2)[
                    (size_t)(n0 + im) * 1600 + chunk * 400 + rem];
            }
            const float4* ws = (const float4*)w;
            float4* wd = (float4*)s_w;
            for (int i = t; i < 2304; i += 256) {
                const int oc = i / 36, rem = i % 36;
                wd[i] = ws[oc * 144 + chunk * 36 + rem];
            }
        }
        __syncthreads();

        for (int ic = 0; ic < 16; ic++) {
#pragma unroll
            for (int ky = 0; ky < 3; ky++) {
                const float* row = s_in + img * 1600 + ic * 100 + (y + ky) * 10;
                float xi[10];
#pragma unroll
                for (int j = 0; j < 10; j++) xi[j] = row[j];
#pragma unroll
                for (int o = 0; o < 8; o++) {
                    const float* wp = s_w + (ocg * 8 + o) * 144 + ic * 9 + ky * 3;
                    float w0 = wp[0], w1 = wp[1], w2 = wp[2];
#pragma unroll
                    for (int j = 0; j < 8; j++)
                        acc[o][j] += xi[j] * w0 + xi[j + 1] * w1 + xi[j + 2] * w2;
                }
            }
        }
    }

    // PReLU + 2x2 pool: vertical pair via shfl_xor(1) (y bit0 = lane bit0)
    const int y2 = y >> 1;
#pragma unroll
    for (int o = 0; o < 8; o++) {
        const int oc = ocg * 8 + o;
        const float b0 = s_b[oc], al = s_a[oc];
        float v[8];
#pragma unroll
        for (int j = 0; j < 8; j++) {
            float u = acc[o][j] + b0;
            v[j] = u >= 0.f ? u : al * u;
        }
        float m[8];
#pragma unroll
        for (int j = 0; j < 8; j++)
            m[j] = fmaxf(v[j], __shfl_xor_sync(0xffffffffu, v[j], 1));
        if ((y & 1) == 0) {
            float4 p;
            p.x = fmaxf(m[0], m[1]);
            p.y = fmaxf(m[2], m[3]);
            p.z = fmaxf(m[4], m[5]);
            p.w = fmaxf(m[6], m[7]);
            *(float4*)(g_B3 + ((size_t)(n0 + img) * 64 + oc) * 16 + y2 * 4) = p;
        }
    }
}

// ---------------------------------------------------------------------------
// K6: conv4 (64->128,2x2)+PReLU+permute flatten. Grid (NIMG/8, 2): block =
// (8 images, oc-half of 64). 2 oc per thread, transposed weights [ic][oc][4].
// smem ~99KB -> 2 CTAs/SM.
// ---------------------------------------------------------------------------
#define K6_SMEM_FLOATS (8192 + 16384 + 64 + 64)
__global__ __launch_bounds__(256, 2) void k6_conv4(
    const float* __restrict__ w, const float* __restrict__ bias,
    const float* __restrict__ alpha)
{
    extern __shared__ float sm6[];
    float* s_in = sm6;             // 8*64*16
    float* s_w  = sm6 + 8192;      // [ic 64][oc 64][4]
    float* s_b  = s_w + 16384;     // 64
    float* s_a  = s_b + 64;

    const int n0 = blockIdx.x * 8;
    const int och = blockIdx.y;    // oc half: 0/1
    const int t = threadIdx.x;
    {
        const float4* src = (const float4*)g_B3 + (size_t)n0 * 256;
        float4* dst = (float4*)s_in;
        for (int i = t; i < 2048; i += 256) dst[i] = src[i];
        const float4* ws = (const float4*)(w + (size_t)och * 64 * 256);
        float4* wd = (float4*)s_w;
        for (int j = t; j < 4096; j += 256) {
            const int oc = j >> 6, ic = j & 63;
            wd[ic * 64 + oc] = ws[oc * 64 + ic];
        }
        if (t < 64) {
            s_b[t] = bias[och * 64 + t];
            s_a[t] = alpha[och * 64 + t];
        }
    }
    __syncthreads();

    const int img = t >> 5;        // 0..7
    const int ocp = t & 31;        // oc pair: local oc {2*ocp, 2*ocp+1}
    float acc[2][9];
#pragma unroll
    for (int p = 0; p < 2; p++)
#pragma unroll
        for (int i = 0; i < 9; i++) acc[p][i] = 0.f;

    for (int ic = 0; ic < 64; ic++) {
        const float* ib = s_in + img * 1024 + ic * 16;
        float xi[16];
#pragma unroll
        for (int q = 0; q < 4; q++) {
            float4 xv = *(const float4*)(ib + q * 4);
            xi[q * 4 + 0] = xv.x; xi[q * 4 + 1] = xv.y;
            xi[q * 4 + 2] = xv.z; xi[q * 4 + 3] = xv.w;
        }
        const float* wp = s_w + (ic * 64 + ocp * 2) * 4;
        float4 w0 = *(const float4*)wp;       // oc even: w00 w01 w10 w11
        float4 w1 = *(const float4*)(wp + 4); // oc odd
#pragma unroll
        for (int h = 0; h < 3; h++)
#pragma unroll
            for (int ww = 0; ww < 3; ww++) {
                const float x00 = xi[h * 4 + ww];
                const float x01 = xi[h * 4 + ww + 1];
                const float x10 = xi[(h + 1) * 4 + ww];
                const float x11 = xi[(h + 1) * 4 + ww + 1];
                acc[0][h * 3 + ww] += x00 * w0.x + x01 * w0.y + x10 * w0.z + x11 * w0.w;
                acc[1][h * 3 + ww] += x00 * w1.x + x01 * w1.y + x10 * w1.z + x11 * w1.w;
            }
    }

    float* ob = g_B4 + (size_t)(n0 + img) * 1152;
#pragma unroll
    for (int p = 0; p < 2; p++) {
        const int ocl = ocp * 2 + p;
        const int oc = och * 64 + ocl;
        const float b0 = s_b[ocl], al = s_a[ocl];
#pragma unroll
        for (int h = 0; h < 3; h++)
#pragma unroll
            for (int ww = 0; ww < 3; ww++) {
                float v = acc[p][h * 3 + ww] + b0;
                v = v >= 0.f ? v : al * v;
                ob[ww * 384 + h * 128 + oc] = v;
            }
    }
}

// ---------------------------------------------------------------------------
// K7: fc5 GEMM [2048,1152] x [256,1152]^T + bias + PReLU, ping-pong buffers.
// ---------------------------------------------------------------------------
__global__ __launch_bounds__(256) void k7_fc5(
    const float* __restrict__ W, const float* __restrict__ bias,
    const float* __restrict__ alpha)
{
    __shared__ float As[2][16][64];
    __shared__ float Bs[2][16][64];
    const int tid = threadIdx.x;
    const int bm = blockIdx.x, bn = blockIdx.y;
    const int tx = tid & 15, ty = tid >> 4;
    const int lr = tid >> 2;
    const int lq = (tid & 3) * 4;

    const float* Ab = g_B4 + (size_t)(bm * 64 + lr) * 1152 + lq;
    const float* Wb = W + (size_t)(bn * 64 + lr) * 1152 + lq;

    float acc[4][4];
#pragma unroll
    for (int i = 0; i < 4; i++)
#pragma unroll
        for (int j = 0; j < 4; j++) acc[i][j] = 0.f;

    {
        float4 av = *(const float4*)Ab;
        float4 wv = *(const float4*)Wb;
        As[0][lq + 0][lr] = av.x; As[0][lq + 1][lr] = av.y;
        As[0][lq + 2][lr] = av.z; As[0][lq + 3][lr] = av.w;
        Bs[0][lq + 0][lr] = wv.x; Bs[0][lq + 1][lr] = wv.y;
        Bs[0][lq + 2][lr] = wv.z; Bs[0][lq + 3][lr] = wv.w;
    }
    __syncthreads();

    int buf = 0;
    for (int k0 = 0; k0 < 1152; k0 += 16) {
        const bool more = (k0 + 16) < 1152;
        float4 nav, nwv;
        if (more) {
            nav = *(const float4*)(Ab + k0 + 16);
            nwv = *(const float4*)(Wb + k0 + 16);
        }
#pragma unroll
        for (int k = 0; k < 16; k++) {
            float ar[4], br[4];
#pragma unroll
            for (int i = 0; i < 4; i++) ar[i] = As[buf][k][ty * 4 + i];
#pragma unroll
            for (int j = 0; j < 4; j++) br[j] = Bs[buf][k][tx * 4 + j];
#pragma unroll
            for (int i = 0; i < 4; i++)
#pragma unroll
                for (int j = 0; j < 4; j++) acc[i][j] += ar[i] * br[j];
        }
        if (more) {
            const int nb = buf ^ 1;
            As[nb][lq + 0][lr] = nav.x; As[nb][lq + 1][lr] = nav.y;
            As[nb][lq + 2][lr] = nav.z; As[nb][lq + 3][lr] = nav.w;
            Bs[nb][lq + 0][lr] = nwv.x; Bs[nb][lq + 1][lr] = nwv.y;
            Bs[nb][lq + 2][lr] = nwv.z; Bs[nb][lq + 3][lr] = nwv.w;
            __syncthreads();
            buf = nb;
        }
    }
#pragma unroll
    for (int i = 0; i < 4; i++) {
        const int nn = bm * 64 + ty * 4 + i;
#pragma unroll
        for (int j = 0; j < 4; j++) {
            const int o = bn * 64 + tx * 4 + j;
            float v = acc[i][j] + bias[o];
            v = v >= 0.f ? v : alpha[o] * v;
            g_B5[(size_t)nn * 256 + o] = v;
        }
    }
}

// ---------------------------------------------------------------------------
// K8: heads. One warp per image. out layout: [b: N*4 | c: N*10 | a: N*2]
// ---------------------------------------------------------------------------
__global__ __launch_bounds__(256) void k8_heads(
    const float* __restrict__ w1, const float* __restrict__ b1,
    const float* __restrict__ w2, const float* __restrict__ b2,
    const float* __restrict__ w3, const float* __restrict__ b3,
    float* __restrict__ out)
{
    const int warp = (blockIdx.x * 256 + threadIdx.x) >> 5;
    const int lane = threadIdx.x & 31;
    if (warp >= NIMG) return;
    const float* hv = g_B5 + (size_t)warp * 256;
    float hr[8];
#pragma unroll
    for (int j = 0; j < 8; j++) hr[j] = hv[lane + j * 32];

    auto dot = [&](const float* wrow) {
        float s = 0.f;
#pragma unroll
        for (int j = 0; j < 8; j++) s += hr[j] * wrow[lane + j * 32];
#pragma unroll
        for (int off = 16; off; off >>= 1) s += __shfl_xor_sync(0xffffffffu, s, off);
        return s;
    };

    float* out_b = out;
    float* out_c = out + (size_t)NIMG * 4;
    float* out_a = out + (size_t)NIMG * 14;

    float l0 = dot(w1) + b1[0];
    float l1 = dot(w1 + 256) + b1[1];
    float mx = fmaxf(l0, l1);
    float e0 = expf(l0 - mx), e1 = expf(l1 - mx);
    float inv = 1.f / (e0 + e1);
    if (lane == 0) {
        out_a[warp * 2 + 0] = e0 * inv;
        out_a[warp * 2 + 1] = e1 * inv;
    }
#pragma unroll
    for (int o = 0; o < 4; o++) {
        float v = dot(w2 + o * 256) + b2[o];
        if (lane == 0) out_b[warp * 4 + o] = v;
    }
#pragma unroll
    for (int o = 0; o < 10; o++) {
        float v = dot(w3 + o * 256) + b3[o];
        if (lane == 0) out_c[warp * 10 + o] = v;
    }
}

// ---------------------------------------------------------------------------
extern "C" void kernel_launch(void* const* d_in, const int* in_sizes, int n_in,
                              void* d_out, int out_size)
{
    const float* x    = (const float*)d_in[0];
    const float* c1w  = (const float*)d_in[1];
    const float* c1b  = (const float*)d_in[2];
    const float* a1   = (const float*)d_in[3];
    const float* c2w  = (const float*)d_in[4];
    const float* c2b  = (const float*)d_in[5];
    const float* a2   = (const float*)d_in[6];
    const float* c3w  = (const float*)d_in[7];
    const float* c3b  = (const float*)d_in[8];
    const float* a3   = (const float*)d_in[9];
    const float* c4w  = (const float*)d_in[10];
    const float* c4b  = (const float*)d_in[11];
    const float* a4   = (const float*)d_in[12];
    const float* d5w  = (const float*)d_in[13];
    const float* d5b  = (const float*)d_in[14];
    const float* a5   = (const float*)d_in[15];
    const float* d61w = (const float*)d_in[16];
    const float* d61b = (const float*)d_in[17];
    const float* d62w = (const float*)d_in[18];
    const float* d62b = (const float*)d_in[19];
    const float* d63w = (const float*)d_in[20];
    const float* d63b = (const float*)d_in[21];
    float* out = (float*)d_out;

    cudaFuncSetAttribute(k1_conv1_pool, cudaFuncAttributeMaxDynamicSharedMemorySize,
                         K1_SMEM_FLOATS * 4);
    cudaFuncSetAttribute(k2_conv2_pool, cudaFuncAttributeMaxDynamicSharedMemorySize,
                         K2_SMEM_FLOATS * 4);
    cudaFuncSetAttribute(k4_conv3_pool, cudaFuncAttributeMaxDynamicSharedMemorySize,
                         K4_SMEM_FLOATS * 4);
    cudaFuncSetAttribute(k6_conv4, cudaFuncAttributeMaxDynamicSharedMemorySize,
                         K6_SMEM_FLOATS * 4);

    k1_conv1_pool<<<dim3(NIMG, 4), 288, K1_SMEM_FLOATS * 4>>>(x, c1w, c1b, a1);
    k2_conv2_pool<<<dim3(NIMG, 2), 256, K2_SMEM_FLOATS * 4>>>(c2w, c2b, a2);
    k4_conv3_pool<<<NIMG / 4, 256, K4_SMEM_FLOATS * 4>>>(c3w, c3b, a3);
    k6_conv4<<<dim3(NIMG / 8, 2), 256, K6_SMEM_FLOATS * 4>>>(c4w, c4b, a4);
    k7_fc5<<<dim3(NIMG / 64, 256 / 64), 256>>>(d5w, d5b, a5);
    k8_heads<<<(NIMG * 32) / 256, 256>>>(d61w, d61b, d62w, d62b, d63w, d63b, out);
}

// round 5
// speedup vs baseline: 4.6129x; 1.3934x over previous
#include <cuda_runtime.h>
#include <cuda_bf16.h>
#include <math.h>

// ---------------------------------------------------------------------------
// MTCNN ONet forward, N=2048. Round 5: conv2 -> tf32 mma.sync implicit GEMM.
//  K1: conv1+PReLU+pool(3,2,ceil)  48->23   fp32        -> g_B1
//  K2: conv2+PReLU+pool(3,2)       23->10   TF32 MMA    -> g_B2
//  K4: conv3+PReLU+pool(2,2)       10->4    fp32        -> g_B3
//  K6: conv4+PReLU+permute flatten 4x4->1152 fp32       -> g_B4
//  K7: fc5 GEMM+PReLU                                    -> g_B5
//  K8: heads -> d_out [b|c|a]
// ---------------------------------------------------------------------------

#define NIMG 2048

__device__ float g_B1[(size_t)NIMG * 32 * 23 * 23];
__device__ float g_B2[(size_t)NIMG * 64 * 10 * 10];
__device__ float g_B3[(size_t)NIMG * 64 * 4 * 4];
__device__ float g_B4[(size_t)NIMG * 1152];
__device__ float g_B5[(size_t)NIMG * 256];

#define NEG_INF (-1e30f)

__device__ __forceinline__ unsigned f2tf32(float f) {
    unsigned u;
    asm("cvt.rna.tf32.f32 %0, %1;" : "=r"(u) : "f"(f));
    return u;
}

__device__ __forceinline__ void mma_tf32(float c[4],
    unsigned a0, unsigned a1, unsigned a2, unsigned a3,
    unsigned b0, unsigned b1)
{
    asm volatile(
        "mma.sync.aligned.m16n8k8.row.col.f32.tf32.tf32.f32 "
        "{%0,%1,%2,%3}, {%4,%5,%6,%7}, {%8,%9}, {%0,%1,%2,%3};"
        : "+f"(c[0]), "+f"(c[1]), "+f"(c[2]), "+f"(c[3])
        : "r"(a0), "r"(a1), "r"(a2), "r"(a3), "r"(b0), "r"(b1));
}

// ---------------------------------------------------------------------------
// K1: conv1 + PReLU + pool1. Grid (NIMG, 4), 288 threads, 2 CTAs/SM. (fp32)
// ---------------------------------------------------------------------------
#define K1_SMEM_FLOATS (6912 + 16928 + 216 + 8 + 8)
__global__ __launch_bounds__(288, 2) void k1_conv1_pool(
    const float* __restrict__ x, const float* __restrict__ w,
    const float* __restrict__ bias, const float* __restrict__ alpha)
{
    extern __shared__ float sm1[];
    float* s_in = sm1;            // 3*48*48
    float* s_cv = sm1 + 6912;     // 8*46*46
    float* s_w  = s_cv + 16928;   // 8*27
    float* s_b  = s_w + 216;
    float* s_a  = s_b + 8;

    const int n = blockIdx.x;
    const int ocg = blockIdx.y;
    const int tid = threadIdx.x;
    {
        const float4* src = (const float4*)(x + (size_t)n * 6912);
        float4* dst = (float4*)s_in;
        for (int i = tid; i < 6912 / 4; i += 288) dst[i] = src[i];
        if (tid < 216) s_w[tid] = w[ocg * 216 + tid];
        if (tid < 8) {
            s_b[tid] = bias[ocg * 8 + tid];
            s_a[tid] = alpha[ocg * 8 + tid];
        }
    }
    __syncthreads();

    if (tid < 276) {
        const int y = tid / 6;
        const int xg = (tid % 6) * 8;

        float acc[8][8];
#pragma unroll
        for (int o = 0; o < 8; o++)
#pragma unroll
            for (int j = 0; j < 8; j++) acc[o][j] = 0.f;

#pragma unroll
        for (int ic = 0; ic < 3; ic++) {
#pragma unroll
            for (int ky = 0; ky < 3; ky++) {
                const float* row = s_in + ic * 2304 + (y + ky) * 48;
                float xi[10];
#pragma unroll
                for (int j = 0; j < 10; j++) {
                    int c = xg + j;
                    xi[j] = row[c > 47 ? 47 : c];
                }
#pragma unroll
                for (int o = 0; o < 8; o++) {
                    const float* wp = s_w + o * 27 + ic * 9 + ky * 3;
                    float w0 = wp[0], w1 = wp[1], w2 = wp[2];
#pragma unroll
                    for (int j = 0; j < 8; j++)
                        acc[o][j] += xi[j] * w0 + xi[j + 1] * w1 + xi[j + 2] * w2;
                }
            }
        }
#pragma unroll
        for (int o = 0; o < 8; o++) {
            const float b0 = s_b[o], al = s_a[o];
            float* orow = s_cv + o * 2116 + y * 46;
#pragma unroll
            for (int j = 0; j < 8; j++) {
                const int xx = xg + j;
                if (xx < 46) {
                    float v = acc[o][j] + b0;
                    orow[xx] = v >= 0.f ? v : al * v;
                }
            }
        }
    }
    __syncthreads();

    float* ob = g_B1 + ((size_t)n * 32 + ocg * 8) * 529;
    for (int i = tid; i < 8 * 529; i += 288) {
        const int o = i / 529;
        const int rem = i % 529;
        const int py = rem / 23;
        const int px = rem % 23;
        const float* base = s_cv + o * 2116;
        float m = NEG_INF;
#pragma unroll
        for (int ky = 0; ky < 3; ky++) {
            int cy = py * 2 + ky; cy = cy > 45 ? 45 : cy;
#pragma unroll
            for (int kx = 0; kx < 3; kx++) {
                int cx = px * 2 + kx; cx = cx > 45 ? 45 : cx;
                m = fmaxf(m, base[cy * 46 + cx]);
            }
        }
        ob[i] = m;
    }
}

// ---------------------------------------------------------------------------
// K2: conv2 + PReLU + pool2 via TF32 mma. One image/block, 448 threads.
// Implicit GEMM: M=448(441), N=64, K=288. Warp w owns m-tiles {2w, 2w+1}.
// smem: s_in [32][23][24] tf32, s_w [288][72] tf32 (k-major, conflict-free),
// col_off[288], bias/alpha. Epilogue overlays conv output, fused 3x3/2 pool.
// ---------------------------------------------------------------------------
#define K2_STW 72
#define K2_SIN_SZ 17728              // 32*552 + pad
#define K2_SW_OFF K2_SIN_SZ          // 17728
#define K2_SW_SZ (288 * K2_STW)      // 20736
#define K2_OFF_OFF (K2_SW_OFF + K2_SW_SZ)   // 38464
#define K2_B_OFF (K2_OFF_OFF + 288)         // 38752
#define K2_A_OFF (K2_B_OFF + 64)            // 38816
#define K2_SMEM_FLOATS (K2_A_OFF + 64)      // 38880 -> 155520 B
#define K2_CV_STRIDE 448

__global__ __launch_bounds__(448, 1) void k2_conv2_pool(
    const float* __restrict__ w, const float* __restrict__ bias,
    const float* __restrict__ alpha)
{
    extern __shared__ float sm2[];
    float* s_in = sm2;
    float* s_w  = sm2 + K2_SW_OFF;
    int*   s_off = (int*)(sm2 + K2_OFF_OFF);
    float* s_b  = sm2 + K2_B_OFF;
    float* s_a  = sm2 + K2_A_OFF;
    float* s_cv = sm2;               // overlay [64][448], 28672 < 38464

    const int n = blockIdx.x;
    const int t = threadIdx.x;

    // ---- stage input (tf32) into [ic][y][24] ----
    {
        const float* src = g_B1 + (size_t)n * 16928;
        for (int i = t; i < 16928; i += 448) {
            const int ic = i / 529;
            const int r = i - ic * 529;
            const int y = r / 23;
            const int x = r - y * 23;
            ((unsigned*)s_in)[ic * 552 + y * 24 + x] = f2tf32(src[i]);
        }
        // weights [oc][288] -> s_w[k][oc] (tf32)
        for (int i = t; i < 18432; i += 448) {
            const int oc = i / 288;
            const int k = i - oc * 288;
            ((unsigned*)s_w)[k * K2_STW + oc] = f2tf32(w[i]);
        }
        if (t < 288) {
            const int k = t;
            const int ic = k / 9;
            const int r = k - ic * 9;
            s_off[k] = ic * 552 + (r / 3) * 24 + (r % 3);
        }
        if (t < 64) {
            s_b[t] = bias[t];
            s_a[t] = alpha[t];
        }
    }
    __syncthreads();

    const int warp = t >> 5;
    const int lane = t & 31;
    const int g = lane >> 2;       // 0..7
    const int tq = lane & 3;       // 0..3

    // row base addresses for the two m-tiles (clamped; invalid m discarded)
    int rb[2][2];
    int mrow[2][2];
#pragma unroll
    for (int mi = 0; mi < 2; mi++) {
        const int mt = 2 * warp + mi;
        int m0 = mt * 16 + g;
        int m1 = m0 + 8;
        mrow[mi][0] = m0; mrow[mi][1] = m1;
        int c0 = m0 > 440 ? 440 : m0;
        int c1 = m1 > 440 ? 440 : m1;
        rb[mi][0] = (c0 / 21) * 24 + (c0 % 21);
        rb[mi][1] = (c1 / 21) * 24 + (c1 % 21);
    }

    float c[2][8][4];
#pragma unroll
    for (int mi = 0; mi < 2; mi++)
#pragma unroll
        for (int nt = 0; nt < 8; nt++)
#pragma unroll
            for (int q = 0; q < 4; q++) c[mi][nt][q] = 0.f;

    const unsigned* u_in = (const unsigned*)s_in;
    const unsigned* u_w = (const unsigned*)s_w;

    for (int kt = 0; kt < 36; kt++) {
        const int k0 = kt * 8 + tq;
        const int off0 = s_off[k0];
        const int off1 = s_off[k0 + 4];

        unsigned b0[8], b1[8];
        const unsigned* wb = u_w + k0 * K2_STW + g;
#pragma unroll
        for (int nt = 0; nt < 8; nt++) {
            b0[nt] = wb[nt * 8];
            b1[nt] = wb[4 * K2_STW + nt * 8];
        }
#pragma unroll
        for (int mi = 0; mi < 2; mi++) {
            const unsigned a0 = u_in[rb[mi][0] + off0];
            const unsigned a1 = u_in[rb[mi][1] + off0];
            const unsigned a2 = u_in[rb[mi][0] + off1];
            const unsigned a3 = u_in[rb[mi][1] + off1];
#pragma unroll
            for (int nt = 0; nt < 8; nt++)
                mma_tf32(c[mi][nt], a0, a1, a2, a3, b0[nt], b1[nt]);
        }
    }
    __syncthreads();   // all smem reads done; overlay becomes writable

    // ---- epilogue: bias + PReLU -> s_cv[oc][448] (m = y*21+x) ----
#pragma unroll
    for (int mi = 0; mi < 2; mi++) {
#pragma unroll
        for (int nt = 0; nt < 8; nt++) {
            const int oc0 = nt * 8 + 2 * tq;
            const int oc1 = oc0 + 1;
            const float b00 = s_b[oc0], a00 = s_a[oc0];
            const float b01 = s_b[oc1], a01 = s_a[oc1];
#pragma unroll
            for (int h = 0; h < 2; h++) {
                const int m = mrow[mi][h];
                if (m < 441) {
                    float v0 = c[mi][nt][2 * h + 0] + b00;
                    float v1 = c[mi][nt][2 * h + 1] + b01;
                    s_cv[oc0 * K2_CV_STRIDE + m] = v0 >= 0.f ? v0 : a00 * v0;
                    s_cv[oc1 * K2_CV_STRIDE + m] = v1 >= 0.f ? v1 : a01 * v1;
                }
            }
        }
    }
    __syncthreads();

    // ---- pool(3,2): 21 -> 10 ----
    float* ob = g_B2 + (size_t)n * 6400;
    for (int i = t; i < 6400; i += 448) {
        const int oc = i / 100;
        const int r = i - oc * 100;
        const int py = r / 10;
        const int px = r - py * 10;
        const float* base = s_cv + oc * K2_CV_STRIDE + (py * 2) * 21 + px * 2;
        float m = NEG_INF;
#pragma unroll
        for (int ky = 0; ky < 3; ky++)
#pragma unroll
            for (int kx = 0; kx < 3; kx++)
                m = fmaxf(m, base[ky * 21 + kx]);
        ob[i] = m;
    }
}

// ---------------------------------------------------------------------------
// K4: conv3 + PReLU + pool3(2,2). 4 img/block, 256 thr, grid 512. (fp32)
// ---------------------------------------------------------------------------
#define K4_SMEM_FLOATS (6400 + 9216 + 64 + 64)
__global__ __launch_bounds__(256) void k4_conv3_pool(
    const float* __restrict__ w, const float* __restrict__ bias,
    const float* __restrict__ alpha)
{
    extern __shared__ float sm4[];
    float* s_in = sm4;             // 4 img * 16 ic * 100
    float* s_w  = sm4 + 6400;      // 64 oc * 16 ic * 9
    float* s_b  = s_w + 9216;
    float* s_a  = s_b + 64;

    const int n0 = blockIdx.x * 4;
    const int t = threadIdx.x;
    const int img = t >> 6;
    const int ocg = (t >> 3) & 7;
    const int y = t & 7;

    if (t < 64) {
        s_b[t] = bias[t];
        s_a[t] = alpha[t];
    }

    float acc[8][8];
#pragma unroll
    for (int o = 0; o < 8; o++)
#pragma unroll
        for (int j = 0; j < 8; j++) acc[o][j] = 0.f;

    for (int chunk = 0; chunk < 4; chunk++) {
        __syncthreads();
        {
            float4* dst = (float4*)s_in;
            for (int i = t; i < 1600; i += 256) {
                const int im = i / 400, rem = i % 400;
                dst[i] = ((const float4*)g_B2)[
                    (size_t)(n0 + im) * 1600 + chunk * 400 + rem];
            }
            const float4* ws = (const float4*)w;
            float4* wd = (float4*)s_w;
            for (int i = t; i < 2304; i += 256) {
                const int oc = i / 36, rem = i % 36;
                wd[i] = ws[oc * 144 + chunk * 36 + rem];
            }
        }
        __syncthreads();

        for (int ic = 0; ic < 16; ic++) {
#pragma unroll
            for (int ky = 0; ky < 3; ky++) {
                const float* row = s_in + img * 1600 + ic * 100 + (y + ky) * 10;
                float xi[10];
#pragma unroll
                for (int j = 0; j < 10; j++) xi[j] = row[j];
#pragma unroll
                for (int o = 0; o < 8; o++) {
                    const float* wp = s_w + (ocg * 8 + o) * 144 + ic * 9 + ky * 3;
                    float w0 = wp[0], w1 = wp[1], w2 = wp[2];
#pragma unroll
                    for (int j = 0; j < 8; j++)
                        acc[o][j] += xi[j] * w0 + xi[j + 1] * w1 + xi[j + 2] * w2;
                }
            }
        }
    }

    const int y2 = y >> 1;
#pragma unroll
    for (int o = 0; o < 8; o++) {
        const int oc = ocg * 8 + o;
        const float b0 = s_b[oc], al = s_a[oc];
        float v[8];
#pragma unroll
        for (int j = 0; j < 8; j++) {
            float u = acc[o][j] + b0;
            v[j] = u >= 0.f ? u : al * u;
        }
        float m[8];
#pragma unroll
        for (int j = 0; j < 8; j++)
            m[j] = fmaxf(v[j], __shfl_xor_sync(0xffffffffu, v[j], 1));
        if ((y & 1) == 0) {
            float4 p;
            p.x = fmaxf(m[0], m[1]);
            p.y = fmaxf(m[2], m[3]);
            p.z = fmaxf(m[4], m[5]);
            p.w = fmaxf(m[6], m[7]);
            *(float4*)(g_B3 + ((size_t)(n0 + img) * 64 + oc) * 16 + y2 * 4) = p;
        }
    }
}

// ---------------------------------------------------------------------------
// K6: conv4 (64->128,2x2)+PReLU+permute flatten. Grid (NIMG/8, 2). (fp32)
// ---------------------------------------------------------------------------
#define K6_SMEM_FLOATS (8192 + 16384 + 64 + 64)
__global__ __launch_bounds__(256, 2) void k6_conv4(
    const float* __restrict__ w, const float* __restrict__ bias,
    const float* __restrict__ alpha)
{
    extern __shared__ float sm6[];
    float* s_in = sm6;             // 8*64*16
    float* s_w  = sm6 + 8192;      // [ic 64][oc 64][4]
    float* s_b  = s_w + 16384;
    float* s_a  = s_b + 64;

    const int n0 = blockIdx.x * 8;
    const int och = blockIdx.y;
    const int t = threadIdx.x;
    {
        const float4* src = (const float4*)g_B3 + (size_t)n0 * 256;
        float4* dst = (float4*)s_in;
        for (int i = t; i < 2048; i += 256) dst[i] = src[i];
        const float4* ws = (const float4*)(w + (size_t)och * 64 * 256);
        float4* wd = (float4*)s_w;
        for (int j = t; j < 4096; j += 256) {
            const int oc = j >> 6, ic = j & 63;
            wd[ic * 64 + oc] = ws[oc * 64 + ic];
        }
        if (t < 64) {
            s_b[t] = bias[och * 64 + t];
            s_a[t] = alpha[och * 64 + t];
        }
    }
    __syncthreads();

    const int img = t >> 5;
    const int ocp = t & 31;
    float acc[2][9];
#pragma unroll
    for (int p = 0; p < 2; p++)
#pragma unroll
        for (int i = 0; i < 9; i++) acc[p][i] = 0.f;

    for (int ic = 0; ic < 64; ic++) {
        const float* ib = s_in + img * 1024 + ic * 16;
        float xi[16];
#pragma unroll
        for (int q = 0; q < 4; q++) {
            float4 xv = *(const float4*)(ib + q * 4);
            xi[q * 4 + 0] = xv.x; xi[q * 4 + 1] = xv.y;
            xi[q * 4 + 2] = xv.z; xi[q * 4 + 3] = xv.w;
        }
        const float* wp = s_w + (ic * 64 + ocp * 2) * 4;
        float4 w0 = *(const float4*)wp;
        float4 w1 = *(const float4*)(wp + 4);
#pragma unroll
        for (int h = 0; h < 3; h++)
#pragma unroll
            for (int ww = 0; ww < 3; ww++) {
                const float x00 = xi[h * 4 + ww];
                const float x01 = xi[h * 4 + ww + 1];
                const float x10 = xi[(h + 1) * 4 + ww];
                const float x11 = xi[(h + 1) * 4 + ww + 1];
                acc[0][h * 3 + ww] += x00 * w0.x + x01 * w0.y + x10 * w0.z + x11 * w0.w;
                acc[1][h * 3 + ww] += x00 * w1.x + x01 * w1.y + x10 * w1.z + x11 * w1.w;
            }
    }

    float* ob = g_B4 + (size_t)(n0 + img) * 1152;
#pragma unroll
    for (int p = 0; p < 2; p++) {
        const int ocl = ocp * 2 + p;
        const int oc = och * 64 + ocl;
        const float b0 = s_b[ocl], al = s_a[ocl];
#pragma unroll
        for (int h = 0; h < 3; h++)
#pragma unroll
            for (int ww = 0; ww < 3; ww++) {
                float v = acc[p][h * 3 + ww] + b0;
                v = v >= 0.f ? v : al * v;
                ob[ww * 384 + h * 128 + oc] = v;
            }
    }
}

// ---------------------------------------------------------------------------
// K7: fc5 GEMM [2048,1152] x [256,1152]^T + bias + PReLU, ping-pong buffers.
// ---------------------------------------------------------------------------
__global__ __launch_bounds__(256) void k7_fc5(
    const float* __restrict__ W, const float* __restrict__ bias,
    const float* __restrict__ alpha)
{
    __shared__ float As[2][16][64];
    __shared__ float Bs[2][16][64];
    const int tid = threadIdx.x;
    const int bm = blockIdx.x, bn = blockIdx.y;
    const int tx = tid & 15, ty = tid >> 4;
    const int lr = tid >> 2;
    const int lq = (tid & 3) * 4;

    const float* Ab = g_B4 + (size_t)(bm * 64 + lr) * 1152 + lq;
    const float* Wb = W + (size_t)(bn * 64 + lr) * 1152 + lq;

    float acc[4][4];
#pragma unroll
    for (int i = 0; i < 4; i++)
#pragma unroll
        for (int j = 0; j < 4; j++) acc[i][j] = 0.f;

    {
        float4 av = *(const float4*)Ab;
        float4 wv = *(const float4*)Wb;
        As[0][lq + 0][lr] = av.x; As[0][lq + 1][lr] = av.y;
        As[0][lq + 2][lr] = av.z; As[0][lq + 3][lr] = av.w;
        Bs[0][lq + 0][lr] = wv.x; Bs[0][lq + 1][lr] = wv.y;
        Bs[0][lq + 2][lr] = wv.z; Bs[0][lq + 3][lr] = wv.w;
    }
    __syncthreads();

    int buf = 0;
    for (int k0 = 0; k0 < 1152; k0 += 16) {
        const bool more = (k0 + 16) < 1152;
        float4 nav, nwv;
        if (more) {
            nav = *(const float4*)(Ab + k0 + 16);
            nwv = *(const float4*)(Wb + k0 + 16);
        }
#pragma unroll
        for (int k = 0; k < 16; k++) {
            float ar[4], br[4];
#pragma unroll
            for (int i = 0; i < 4; i++) ar[i] = As[buf][k][ty * 4 + i];
#pragma unroll
            for (int j = 0; j < 4; j++) br[j] = Bs[buf][k][tx * 4 + j];
#pragma unroll
            for (int i = 0; i < 4; i++)
#pragma unroll
                for (int j = 0; j < 4; j++) acc[i][j] += ar[i] * br[j];
        }
        if (more) {
            const int nb = buf ^ 1;
            As[nb][lq + 0][lr] = nav.x; As[nb][lq + 1][lr] = nav.y;
            As[nb][lq + 2][lr] = nav.z; As[nb][lq + 3][lr] = nav.w;
            Bs[nb][lq + 0][lr] = nwv.x; Bs[nb][lq + 1][lr] = nwv.y;
            Bs[nb][lq + 2][lr] = nwv.z; Bs[nb][lq + 3][lr] = nwv.w;
            __syncthreads();
            buf = nb;
        }
    }
#pragma unroll
    for (int i = 0; i < 4; i++) {
        const int nn = bm * 64 + ty * 4 + i;
#pragma unroll
        for (int j = 0; j < 4; j++) {
            const int o = bn * 64 + tx * 4 + j;
            float v = acc[i][j] + bias[o];
            v = v >= 0.f ? v : alpha[o] * v;
            g_B5[(size_t)nn * 256 + o] = v;
        }
    }
}

// ---------------------------------------------------------------------------
// K8: heads. One warp per image. out layout: [b: N*4 | c: N*10 | a: N*2]
// ---------------------------------------------------------------------------
__global__ __launch_bounds__(256) void k8_heads(
    const float* __restrict__ w1, const float* __restrict__ b1,
    const float* __restrict__ w2, const float* __restrict__ b2,
    const float* __restrict__ w3, const float* __restrict__ b3,
    float* __restrict__ out)
{
    const int warp = (blockIdx.x * 256 + threadIdx.x) >> 5;
    const int lane = threadIdx.x & 31;
    if (warp >= NIMG) return;
    const float* hv = g_B5 + (size_t)warp * 256;
    float hr[8];
#pragma unroll
    for (int j = 0; j < 8; j++) hr[j] = hv[lane + j * 32];

    auto dot = [&](const float* wrow) {
        float s = 0.f;
#pragma unroll
        for (int j = 0; j < 8; j++) s += hr[j] * wrow[lane + j * 32];
#pragma unroll
        for (int off = 16; off; off >>= 1) s += __shfl_xor_sync(0xffffffffu, s, off);
        return s;
    };

    float* out_b = out;
    float* out_c = out + (size_t)NIMG * 4;
    float* out_a = out + (size_t)NIMG * 14;

    float l0 = dot(w1) + b1[0];
    float l1 = dot(w1 + 256) + b1[1];
    float mx = fmaxf(l0, l1);
    float e0 = expf(l0 - mx), e1 = expf(l1 - mx);
    float inv = 1.f / (e0 + e1);
    if (lane == 0) {
        out_a[warp * 2 + 0] = e0 * inv;
        out_a[warp * 2 + 1] = e1 * inv;
    }
#pragma unroll
    for (int o = 0; o < 4; o++) {
        float v = dot(w2 + o * 256) + b2[o];
        if (lane == 0) out_b[warp * 4 + o] = v;
    }
#pragma unroll
    for (int o = 0; o < 10; o++) {
        float v = dot(w3 + o * 256) + b3[o];
        if (lane == 0) out_c[warp * 10 + o] = v;
    }
}

// ---------------------------------------------------------------------------
extern "C" void kernel_launch(void* const* d_in, const int* in_sizes, int n_in,
                              void* d_out, int out_size)
{
    const float* x    = (const float*)d_in[0];
    const float* c1w  = (const float*)d_in[1];
    const float* c1b  = (const float*)d_in[2];
    const float* a1   = (const float*)d_in[3];
    const float* c2w  = (const float*)d_in[4];
    const float* c2b  = (const float*)d_in[5];
    const float* a2   = (const float*)d_in[6];
    const float* c3w  = (const float*)d_in[7];
    const float* c3b  = (const float*)d_in[8];
    const float* a3   = (const float*)d_in[9];
    const float* c4w  = (const float*)d_in[10];
    const float* c4b  = (const float*)d_in[11];
    const float* a4   = (const float*)d_in[12];
    const float* d5w  = (const float*)d_in[13];
    const float* d5b  = (const float*)d_in[14];
    const float* a5   = (const float*)d_in[15];
    const float* d61w = (const float*)d_in[16];
    const float* d61b = (const float*)d_in[17];
    const float* d62w = (const float*)d_in[18];
    const float* d62b = (const float*)d_in[19];
    const float* d63w = (const float*)d_in[20];
    const float* d63b = (const float*)d_in[21];
    float* out = (float*)d_out;

    cudaFuncSetAttribute(k1_conv1_pool, cudaFuncAttributeMaxDynamicSharedMemorySize,
                         K1_SMEM_FLOATS * 4);
    cudaFuncSetAttribute(k2_conv2_pool, cudaFuncAttributeMaxDynamicSharedMemorySize,
                         K2_SMEM_FLOATS * 4);
    cudaFuncSetAttribute(k4_conv3_pool, cudaFuncAttributeMaxDynamicSharedMemorySize,
                         K4_SMEM_FLOATS * 4);
    cudaFuncSetAttribute(k6_conv4, cudaFuncAttributeMaxDynamicSharedMemorySize,
                         K6_SMEM_FLOATS * 4);

    k1_conv1_pool<<<dim3(NIMG, 4), 288, K1_SMEM_FLOATS * 4>>>(x, c1w, c1b, a1);
    k2_conv2_pool<<<NIMG, 448, K2_SMEM_FLOATS * 4>>>(c2w, c2b, a2);
    k4_conv3_pool<<<NIMG / 4, 256, K4_SMEM_FLOATS * 4>>>(c3w, c3b, a3);
    k6_conv4<<<dim3(NIMG / 8, 2), 256, K6_SMEM_FLOATS * 4>>>(c4w, c4b, a4);
    k7_fc5<<<dim3(NIMG / 64, 256 / 64), 256>>>(d5w, d5b, a5);
    k8_heads<<<(NIMG * 32) / 256, 256>>>(d61w, d61b, d62w, d62b, d63w, d63b, out);
}

// round 7
// speedup vs baseline: 4.8720x; 1.0562x over previous
#include <cuda_runtime.h>
#include <cuda_bf16.h>
#include <math.h>

// ---------------------------------------------------------------------------
// MTCNN ONet forward, N=2048. Round 7 (= R6 resubmit after infra failure):
// conv3 + fc5 -> 3xTF32 mma (compensated).
//  K1: conv1+PReLU+pool(3,2,ceil)  48->23   fp32          -> g_B1
//  K2: conv2+PReLU+pool(3,2)       23->10   TF32 MMA      -> g_B2
//  K4: conv3+PReLU+pool(2,2)       10->4    3xTF32 MMA    -> g_B3
//  K6: conv4+PReLU+permute flatten 4x4->1152 fp32         -> g_B4
//  K7: fc5 GEMM+PReLU              3xTF32 MMA             -> g_B5
//  K8: heads -> d_out [b|c|a]
// ---------------------------------------------------------------------------

#define NIMG 2048

__device__ float g_B1[(size_t)NIMG * 32 * 23 * 23];
__device__ float g_B2[(size_t)NIMG * 64 * 10 * 10];
__device__ float g_B3[(size_t)NIMG * 64 * 4 * 4];
__device__ float g_B4[(size_t)NIMG * 1152];
__device__ float g_B5[(size_t)NIMG * 256];

#define NEG_INF (-1e30f)

__device__ __forceinline__ unsigned f2tf32(float f) {
    unsigned u;
    asm("cvt.rna.tf32.f32 %0, %1;" : "=r"(u) : "f"(f));
    return u;
}

__device__ __forceinline__ void mma_tf32(float c[4],
    unsigned a0, unsigned a1, unsigned a2, unsigned a3,
    unsigned b0, unsigned b1)
{
    asm volatile(
        "mma.sync.aligned.m16n8k8.row.col.f32.tf32.tf32.f32 "
        "{%0,%1,%2,%3}, {%4,%5,%6,%7}, {%8,%9}, {%0,%1,%2,%3};"
        : "+f"(c[0]), "+f"(c[1]), "+f"(c[2]), "+f"(c[3])
        : "r"(a0), "r"(a1), "r"(a2), "r"(a3), "r"(b0), "r"(b1));
}

// ---------------------------------------------------------------------------
// K1: conv1 + PReLU + pool1. Grid (NIMG, 4), 288 threads, 2 CTAs/SM. (fp32)
// ---------------------------------------------------------------------------
#define K1_SMEM_FLOATS (6912 + 16928 + 216 + 8 + 8)
__global__ __launch_bounds__(288, 2) void k1_conv1_pool(
    const float* __restrict__ x, const float* __restrict__ w,
    const float* __restrict__ bias, const float* __restrict__ alpha)
{
    extern __shared__ float sm1[];
    float* s_in = sm1;            // 3*48*48
    float* s_cv = sm1 + 6912;     // 8*46*46
    float* s_w  = s_cv + 16928;   // 8*27
    float* s_b  = s_w + 216;
    float* s_a  = s_b + 8;

    const int n = blockIdx.x;
    const int ocg = blockIdx.y;
    const int tid = threadIdx.x;
    {
        const float4* src = (const float4*)(x + (size_t)n * 6912);
        float4* dst = (float4*)s_in;
        for (int i = tid; i < 6912 / 4; i += 288) dst[i] = src[i];
        if (tid < 216) s_w[tid] = w[ocg * 216 + tid];
        if (tid < 8) {
            s_b[tid] = bias[ocg * 8 + tid];
            s_a[tid] = alpha[ocg * 8 + tid];
        }
    }
    __syncthreads();

    if (tid < 276) {
        const int y = tid / 6;
        const int xg = (tid % 6) * 8;

        float acc[8][8];
#pragma unroll
        for (int o = 0; o < 8; o++)
#pragma unroll
            for (int j = 0; j < 8; j++) acc[o][j] = 0.f;

#pragma unroll
        for (int ic = 0; ic < 3; ic++) {
#pragma unroll
            for (int ky = 0; ky < 3; ky++) {
                const float* row = s_in + ic * 2304 + (y + ky) * 48;
                float xi[10];
#pragma unroll
                for (int j = 0; j < 10; j++) {
                    int c = xg + j;
                    xi[j] = row[c > 47 ? 47 : c];
                }
#pragma unroll
                for (int o = 0; o < 8; o++) {
                    const float* wp = s_w + o * 27 + ic * 9 + ky * 3;
                    float w0 = wp[0], w1 = wp[1], w2 = wp[2];
#pragma unroll
                    for (int j = 0; j < 8; j++)
                        acc[o][j] += xi[j] * w0 + xi[j + 1] * w1 + xi[j + 2] * w2;
                }
            }
        }
#pragma unroll
        for (int o = 0; o < 8; o++) {
            const float b0 = s_b[o], al = s_a[o];
            float* orow = s_cv + o * 2116 + y * 46;
#pragma unroll
            for (int j = 0; j < 8; j++) {
                const int xx = xg + j;
                if (xx < 46) {
                    float v = acc[o][j] + b0;
                    orow[xx] = v >= 0.f ? v : al * v;
                }
            }
        }
    }
    __syncthreads();

    float* ob = g_B1 + ((size_t)n * 32 + ocg * 8) * 529;
    for (int i = tid; i < 8 * 529; i += 288) {
        const int o = i / 529;
        const int rem = i % 529;
        const int py = rem / 23;
        const int px = rem % 23;
        const float* base = s_cv + o * 2116;
        float m = NEG_INF;
#pragma unroll
        for (int ky = 0; ky < 3; ky++) {
            int cy = py * 2 + ky; cy = cy > 45 ? 45 : cy;
#pragma unroll
            for (int kx = 0; kx < 3; kx++) {
                int cx = px * 2 + kx; cx = cx > 45 ? 45 : cx;
                m = fmaxf(m, base[cy * 46 + cx]);
            }
        }
        ob[i] = m;
    }
}

// ---------------------------------------------------------------------------
// K2: conv2 + PReLU + pool2 via TF32 mma. One image/block, 448 threads.
// ---------------------------------------------------------------------------
#define K2_STW 72
#define K2_SIN_SZ 17728
#define K2_SW_OFF K2_SIN_SZ
#define K2_SW_SZ (288 * K2_STW)
#define K2_OFF_OFF (K2_SW_OFF + K2_SW_SZ)
#define K2_B_OFF (K2_OFF_OFF + 288)
#define K2_A_OFF (K2_B_OFF + 64)
#define K2_SMEM_FLOATS (K2_A_OFF + 64)
#define K2_CV_STRIDE 448

__global__ __launch_bounds__(448, 1) void k2_conv2_pool(
    const float* __restrict__ w, const float* __restrict__ bias,
    const float* __restrict__ alpha)
{
    extern __shared__ float sm2[];
    float* s_in = sm2;
    float* s_w  = sm2 + K2_SW_OFF;
    int*   s_off = (int*)(sm2 + K2_OFF_OFF);
    float* s_b  = sm2 + K2_B_OFF;
    float* s_a  = sm2 + K2_A_OFF;
    float* s_cv = sm2;

    const int n = blockIdx.x;
    const int t = threadIdx.x;

    {
        const float* src = g_B1 + (size_t)n * 16928;
        for (int i = t; i < 16928; i += 448) {
            const int ic = i / 529;
            const int r = i - ic * 529;
            const int y = r / 23;
            const int x = r - y * 23;
            ((unsigned*)s_in)[ic * 552 + y * 24 + x] = f2tf32(src[i]);
        }
        for (int i = t; i < 18432; i += 448) {
            const int oc = i / 288;
            const int k = i - oc * 288;
            ((unsigned*)s_w)[k * K2_STW + oc] = f2tf32(w[i]);
        }
        if (t < 288) {
            const int k = t;
            const int ic = k / 9;
            const int r = k - ic * 9;
            s_off[k] = ic * 552 + (r / 3) * 24 + (r % 3);
        }
        if (t < 64) {
            s_b[t] = bias[t];
            s_a[t] = alpha[t];
        }
    }
    __syncthreads();

    const int warp = t >> 5;
    const int lane = t & 31;
    const int g = lane >> 2;
    const int tq = lane & 3;

    int rb[2][2];
    int mrow[2][2];
#pragma unroll
    for (int mi = 0; mi < 2; mi++) {
        const int mt = 2 * warp + mi;
        int m0 = mt * 16 + g;
        int m1 = m0 + 8;
        mrow[mi][0] = m0; mrow[mi][1] = m1;
        int c0 = m0 > 440 ? 440 : m0;
        int c1 = m1 > 440 ? 440 : m1;
        rb[mi][0] = (c0 / 21) * 24 + (c0 % 21);
        rb[mi][1] = (c1 / 21) * 24 + (c1 % 21);
    }

    float c[2][8][4];
#pragma unroll
    for (int mi = 0; mi < 2; mi++)
#pragma unroll
        for (int nt = 0; nt < 8; nt++)
#pragma unroll
            for (int q = 0; q < 4; q++) c[mi][nt][q] = 0.f;

    const unsigned* u_in = (const unsigned*)s_in;
    const unsigned* u_w = (const unsigned*)s_w;

    for (int kt = 0; kt < 36; kt++) {
        const int k0 = kt * 8 + tq;
        const int off0 = s_off[k0];
        const int off1 = s_off[k0 + 4];

        unsigned b0[8], b1[8];
        const unsigned* wb = u_w + k0 * K2_STW + g;
#pragma unroll
        for (int nt = 0; nt < 8; nt++) {
            b0[nt] = wb[nt * 8];
            b1[nt] = wb[4 * K2_STW + nt * 8];
        }
#pragma unroll
        for (int mi = 0; mi < 2; mi++) {
            const unsigned a0 = u_in[rb[mi][0] + off0];
            const unsigned a1 = u_in[rb[mi][1] + off0];
            const unsigned a2 = u_in[rb[mi][0] + off1];
            const unsigned a3 = u_in[rb[mi][1] + off1];
#pragma unroll
            for (int nt = 0; nt < 8; nt++)
                mma_tf32(c[mi][nt], a0, a1, a2, a3, b0[nt], b1[nt]);
        }
    }
    __syncthreads();

#pragma unroll
    for (int mi = 0; mi < 2; mi++) {
#pragma unroll
        for (int nt = 0; nt < 8; nt++) {
            const int oc0 = nt * 8 + 2 * tq;
            const int oc1 = oc0 + 1;
            const float b00 = s_b[oc0], a00 = s_a[oc0];
            const float b01 = s_b[oc1], a01 = s_a[oc1];
#pragma unroll
            for (int h = 0; h < 2; h++) {
                const int m = mrow[mi][h];
                if (m < 441) {
                    float v0 = c[mi][nt][2 * h + 0] + b00;
                    float v1 = c[mi][nt][2 * h + 1] + b01;
                    s_cv[oc0 * K2_CV_STRIDE + m] = v0 >= 0.f ? v0 : a00 * v0;
                    s_cv[oc1 * K2_CV_STRIDE + m] = v1 >= 0.f ? v1 : a01 * v1;
                }
            }
        }
    }
    __syncthreads();

    float* ob = g_B2 + (size_t)n * 6400;
    for (int i = t; i < 6400; i += 448) {
        const int oc = i / 100;
        const int r = i - oc * 100;
        const int py = r / 10;
        const int px = r - py * 10;
        const float* base = s_cv + oc * K2_CV_STRIDE + (py * 2) * 21 + px * 2;
        float m = NEG_INF;
#pragma unroll
        for (int ky = 0; ky < 3; ky++)
#pragma unroll
            for (int kx = 0; kx < 3; kx++)
                m = fmaxf(m, base[ky * 21 + kx]);
        ob[i] = m;
    }
}

// ---------------------------------------------------------------------------
// K4: conv3 + PReLU + pool3 via 3xTF32 mma. 4 img/block, 256 thr, grid 512.
// Implicit GEMM M=256 (4img x 8x8), N=64, K=576 in 4 ic-chunks of 144.
// hi/lo split operands -> fp32-grade accuracy (3 MMAs per product term).
// ---------------------------------------------------------------------------
#define K4_INH 0
#define K4_INL 7680
#define K4_WH 15360
#define K4_WL 25728
#define K4_OFFT 36096
#define K4_BO 36240
#define K4_AO 36304
#define K4_SMEM_FLOATS 36368

__global__ __launch_bounds__(256, 1) void k4_conv3_pool(
    const float* __restrict__ w, const float* __restrict__ bias,
    const float* __restrict__ alpha)
{
    extern __shared__ float sm4[];
    unsigned* inh = (unsigned*)(sm4 + K4_INH);   // [4img][16ic][10][12]
    unsigned* inl = (unsigned*)(sm4 + K4_INL);
    unsigned* wh  = (unsigned*)(sm4 + K4_WH);    // [144][72]
    unsigned* wl  = (unsigned*)(sm4 + K4_WL);
    int* s_off    = (int*)(sm4 + K4_OFFT);       // [144]
    float* s_b    = sm4 + K4_BO;
    float* s_a    = sm4 + K4_AO;
    float* s_cv   = sm4;                         // overlay [4img][64oc][64px]

    const int n0 = blockIdx.x * 4;
    const int t = threadIdx.x;
    const int warp = t >> 5;
    const int lane = t & 31;
    const int g = lane >> 2;
    const int tq = lane & 3;

    if (t < 64) {
        s_b[t] = bias[t];
        s_a[t] = alpha[t];
    }
    if (t < 144) {
        const int ic = t / 9;
        const int r = t - ic * 9;
        s_off[t] = ic * 120 + (r / 3) * 12 + (r % 3);
    }

    int rb[2][2];
#pragma unroll
    for (int mi = 0; mi < 2; mi++) {
        const int mt = 2 * warp + mi;
#pragma unroll
        for (int h = 0; h < 2; h++) {
            const int m = mt * 16 + g + 8 * h;
            const int img = m >> 6;
            const int px = m & 63;
            rb[mi][h] = img * 1920 + (px >> 3) * 12 + (px & 7);
        }
    }

    float c[2][8][4];
#pragma unroll
    for (int mi = 0; mi < 2; mi++)
#pragma unroll
        for (int nt = 0; nt < 8; nt++)
#pragma unroll
            for (int q = 0; q < 4; q++) c[mi][nt][q] = 0.f;

    for (int chunk = 0; chunk < 4; chunk++) {
        __syncthreads();
        // stage input (hi/lo tf32)
        for (int i = t; i < 6400; i += 256) {
            const int im = i / 1600;
            const int rem = i - im * 1600;
            const int icl = rem / 100;
            const int r2 = rem - icl * 100;
            const int y = r2 / 10;
            const int xx = r2 - y * 10;
            const float f = g_B2[(size_t)(n0 + im) * 6400 + (chunk * 16 + icl) * 100 + r2];
            const unsigned hb = f2tf32(f);
            const unsigned lb = f2tf32(f - __uint_as_float(hb));
            const int di = im * 1920 + icl * 120 + y * 12 + xx;
            inh[di] = hb;
            inl[di] = lb;
        }
        // stage weights (hi/lo tf32), k-major
        for (int i = t; i < 9216; i += 256) {
            const int oc = i / 144;
            const int k = i - oc * 144;
            const float f = w[oc * 576 + chunk * 144 + k];
            const unsigned hb = f2tf32(f);
            const unsigned lb = f2tf32(f - __uint_as_float(hb));
            wh[k * 72 + oc] = hb;
            wl[k * 72 + oc] = lb;
        }
        __syncthreads();

        for (int kt = 0; kt < 18; kt++) {
            const int k0 = kt * 8 + tq;
            const int off0 = s_off[k0];
            const int off1 = s_off[k0 + 4];

            unsigned bh0[8], bh1[8], bl0[8], bl1[8];
            const unsigned* wbh = wh + k0 * 72 + g;
            const unsigned* wbl = wl + k0 * 72 + g;
#pragma unroll
            for (int nt = 0; nt < 8; nt++) {
                bh0[nt] = wbh[nt * 8];
                bh1[nt] = wbh[4 * 72 + nt * 8];
                bl0[nt] = wbl[nt * 8];
                bl1[nt] = wbl[4 * 72 + nt * 8];
            }
#pragma unroll
            for (int mi = 0; mi < 2; mi++) {
                const unsigned ah0 = inh[rb[mi][0] + off0];
                const unsigned ah1 = inh[rb[mi][1] + off0];
                const unsigned ah2 = inh[rb[mi][0] + off1];
                const unsigned ah3 = inh[rb[mi][1] + off1];
                const unsigned al0 = inl[rb[mi][0] + off0];
                const unsigned al1 = inl[rb[mi][1] + off0];
                const unsigned al2 = inl[rb[mi][0] + off1];
                const unsigned al3 = inl[rb[mi][1] + off1];
#pragma unroll
                for (int nt = 0; nt < 8; nt++) {
                    mma_tf32(c[mi][nt], ah0, ah1, ah2, ah3, bh0[nt], bh1[nt]);
                    mma_tf32(c[mi][nt], ah0, ah1, ah2, ah3, bl0[nt], bl1[nt]);
                    mma_tf32(c[mi][nt], al0, al1, al2, al3, bh0[nt], bh1[nt]);
                }
            }
        }
    }
    __syncthreads();

    // epilogue: bias + PReLU -> s_cv[img][oc][px]
#pragma unroll
    for (int mi = 0; mi < 2; mi++) {
        const int mt = 2 * warp + mi;
#pragma unroll
        for (int nt = 0; nt < 8; nt++) {
            const int oc0 = nt * 8 + 2 * tq;
            const int oc1 = oc0 + 1;
            const float b00 = s_b[oc0], a00 = s_a[oc0];
            const float b01 = s_b[oc1], a01 = s_a[oc1];
#pragma unroll
            for (int h = 0; h < 2; h++) {
                const int m = mt * 16 + g + 8 * h;
                const int img = m >> 6;
                const int px = m & 63;
                float v0 = c[mi][nt][2 * h + 0] + b00;
                float v1 = c[mi][nt][2 * h + 1] + b01;
                s_cv[(img * 64 + oc0) * 64 + px] = v0 >= 0.f ? v0 : a00 * v0;
                s_cv[(img * 64 + oc1) * 64 + px] = v1 >= 0.f ? v1 : a01 * v1;
            }
        }
    }
    __syncthreads();

    // pool 2x2: 8x8 -> 4x4
    for (int i = t; i < 4096; i += 256) {
        const int img = i >> 10;
        const int rem = i & 1023;
        const int oc = rem >> 4;
        const int p = rem & 15;
        const int py = p >> 2;
        const int px = p & 3;
        const float* base = s_cv + (img * 64 + oc) * 64 + py * 16 + px * 2;
        float m = fmaxf(fmaxf(base[0], base[1]), fmaxf(base[8], base[9]));
        g_B3[((size_t)(n0 + img) * 64 + oc) * 16 + p] = m;
    }
}

// ---------------------------------------------------------------------------
// K6: conv4 (64->128,2x2)+PReLU+permute flatten. Grid (NIMG/8, 2). (fp32)
// ---------------------------------------------------------------------------
#define K6_SMEM_FLOATS (8192 + 16384 + 64 + 64)
__global__ __launch_bounds__(256, 2) void k6_conv4(
    const float* __restrict__ w, const float* __restrict__ bias,
    const float* __restrict__ alpha)
{
    extern __shared__ float sm6[];
    float* s_in = sm6;
    float* s_w  = sm6 + 8192;
    float* s_b  = s_w + 16384;
    float* s_a  = s_b + 64;

    const int n0 = blockIdx.x * 8;
    const int och = blockIdx.y;
    const int t = threadIdx.x;
    {
        const float4* src = (const float4*)g_B3 + (size_t)n0 * 256;
        float4* dst = (float4*)s_in;
        for (int i = t; i < 2048; i += 256) dst[i] = src[i];
        const float4* ws = (const float4*)(w + (size_t)och * 64 * 256);
        float4* wd = (float4*)s_w;
        for (int j = t; j < 4096; j += 256) {
            const int oc = j >> 6, ic = j & 63;
            wd[ic * 64 + oc] = ws[oc * 64 + ic];
        }
        if (t < 64) {
            s_b[t] = bias[och * 64 + t];
            s_a[t] = alpha[och * 64 + t];
        }
    }
    __syncthreads();

    const int img = t >> 5;
    const int ocp = t & 31;
    float acc[2][9];
#pragma unroll
    for (int p = 0; p < 2; p++)
#pragma unroll
        for (int i = 0; i < 9; i++) acc[p][i] = 0.f;

    for (int ic = 0; ic < 64; ic++) {
        const float* ib = s_in + img * 1024 + ic * 16;
        float xi[16];
#pragma unroll
        for (int q = 0; q < 4; q++) {
            float4 xv = *(const float4*)(ib + q * 4);
            xi[q * 4 + 0] = xv.x; xi[q * 4 + 1] = xv.y;
            xi[q * 4 + 2] = xv.z; xi[q * 4 + 3] = xv.w;
        }
        const float* wp = s_w + (ic * 64 + ocp * 2) * 4;
        float4 w0 = *(const float4*)wp;
        float4 w1 = *(const float4*)(wp + 4);
#pragma unroll
        for (int h = 0; h < 3; h++)
#pragma unroll
            for (int ww = 0; ww < 3; ww++) {
                const float x00 = xi[h * 4 + ww];
                const float x01 = xi[h * 4 + ww + 1];
                const float x10 = xi[(h + 1) * 4 + ww];
                const float x11 = xi[(h + 1) * 4 + ww + 1];
                acc[0][h * 3 + ww] += x00 * w0.x + x01 * w0.y + x10 * w0.z + x11 * w0.w;
                acc[1][h * 3 + ww] += x00 * w1.x + x01 * w1.y + x10 * w1.z + x11 * w1.w;
            }
    }

    float* ob = g_B4 + (size_t)(n0 + img) * 1152;
#pragma unroll
    for (int p = 0; p < 2; p++) {
        const int ocl = ocp * 2 + p;
        const int oc = och * 64 + ocl;
        const float b0 = s_b[ocl], al = s_a[ocl];
#pragma unroll
        for (int h = 0; h < 3; h++)
#pragma unroll
            for (int ww = 0; ww < 3; ww++) {
                float v = acc[p][h * 3 + ww] + b0;
                v = v >= 0.f ? v : al * v;
                ob[ww * 384 + h * 128 + oc] = v;
            }
    }
}

// ---------------------------------------------------------------------------
// K7: fc5 via 3xTF32 mma. Grid (32, 4), 256 thr. Tile 64x64, k-slab 32.
// ---------------------------------------------------------------------------
__global__ __launch_bounds__(256) void k7_fc5(
    const float* __restrict__ W, const float* __restrict__ bias,
    const float* __restrict__ alpha)
{
    __shared__ unsigned sAh[64 * 36], sAl[64 * 36];
    __shared__ unsigned sBh[64 * 36], sBl[64 * 36];

    const int t = threadIdx.x;
    const int bm = blockIdx.x, bn = blockIdx.y;
    const int warp = t >> 5;
    const int lane = t & 31;
    const int g = lane >> 2;
    const int tq = lane & 3;
    const int w_m = warp & 3;
    const int w_n = warp >> 2;

    float c[4][4];
#pragma unroll
    for (int nt = 0; nt < 4; nt++)
#pragma unroll
        for (int q = 0; q < 4; q++) c[nt][q] = 0.f;

    for (int slab = 0; slab < 36; slab++) {
        const int k0s = slab * 32;
        __syncthreads();
        for (int j = t; j < 512; j += 256) {
            const int m = j >> 3;
            const int kq = (j & 7) * 4;
            float4 v = *(const float4*)(g_B4 + (size_t)(bm * 64 + m) * 1152 + k0s + kq);
            float4 u = *(const float4*)(W + (size_t)(bn * 64 + m) * 1152 + k0s + kq);
            const float va[4] = {v.x, v.y, v.z, v.w};
            const float ua[4] = {u.x, u.y, u.z, u.w};
#pragma unroll
            for (int e = 0; e < 4; e++) {
                unsigned hb = f2tf32(va[e]);
                sAh[m * 36 + kq + e] = hb;
                sAl[m * 36 + kq + e] = f2tf32(va[e] - __uint_as_float(hb));
                unsigned hb2 = f2tf32(ua[e]);
                sBh[m * 36 + kq + e] = hb2;
                sBl[m * 36 + kq + e] = f2tf32(ua[e] - __uint_as_float(hb2));
            }
        }
        __syncthreads();

#pragma unroll
        for (int kt = 0; kt < 4; kt++) {
            const int kk = kt * 8 + tq;
            const int r0 = (w_m * 16 + g) * 36;
            const int r1 = (w_m * 16 + g + 8) * 36;
            const unsigned ah0 = sAh[r0 + kk];
            const unsigned ah1 = sAh[r1 + kk];
            const unsigned ah2 = sAh[r0 + kk + 4];
            const unsigned ah3 = sAh[r1 + kk + 4];
            const unsigned al0 = sAl[r0 + kk];
            const unsigned al1 = sAl[r1 + kk];
            const unsigned al2 = sAl[r0 + kk + 4];
            const unsigned al3 = sAl[r1 + kk + 4];
#pragma unroll
            for (int nt = 0; nt < 4; nt++) {
                const int nr = (w_n * 32 + nt * 8 + g) * 36;
                const unsigned bh0 = sBh[nr + kk];
                const unsigned bh1 = sBh[nr + kk + 4];
                const unsigned bl0 = sBl[nr + kk];
                const unsigned bl1 = sBl[nr + kk + 4];
                mma_tf32(c[nt], ah0, ah1, ah2, ah3, bh0, bh1);
                mma_tf32(c[nt], ah0, ah1, ah2, ah3, bl0, bl1);
                mma_tf32(c[nt], al0, al1, al2, al3, bh0, bh1);
            }
        }
    }

#pragma unroll
    for (int nt = 0; nt < 4; nt++) {
        const int o0 = bn * 64 + w_n * 32 + nt * 8 + 2 * tq;
        const int o1 = o0 + 1;
        const float bi0 = bias[o0], al0 = alpha[o0];
        const float bi1 = bias[o1], al1 = alpha[o1];
#pragma unroll
        for (int h = 0; h < 2; h++) {
            const int m = bm * 64 + w_m * 16 + g + 8 * h;
            float v0 = c[nt][2 * h + 0] + bi0;
            float v1 = c[nt][2 * h + 1] + bi1;
            g_B5[(size_t)m * 256 + o0] = v0 >= 0.f ? v0 : al0 * v0;
            g_B5[(size_t)m * 256 + o1] = v1 >= 0.f ? v1 : al1 * v1;
        }
    }
}

// ---------------------------------------------------------------------------
// K8: heads. One warp per image. out layout: [b: N*4 | c: N*10 | a: N*2]
// ---------------------------------------------------------------------------
__global__ __launch_bounds__(256) void k8_heads(
    const float* __restrict__ w1, const float* __restrict__ b1,
    const float* __restrict__ w2, const float* __restrict__ b2,
    const float* __restrict__ w3, const float* __restrict__ b3,
    float* __restrict__ out)
{
    const int warp = (blockIdx.x * 256 + threadIdx.x) >> 5;
    const int lane = threadIdx.x & 31;
    if (warp >= NIMG) return;
    const float* hv = g_B5 + (size_t)warp * 256;
    float hr[8];
#pragma unroll
    for (int j = 0; j < 8; j++) hr[j] = hv[lane + j * 32];

    auto dot = [&](const float* wrow) {
        float s = 0.f;
#pragma unroll
        for (int j = 0; j < 8; j++) s += hr[j] * wrow[lane + j * 32];
#pragma unroll
        for (int off = 16; off; off >>= 1) s += __shfl_xor_sync(0xffffffffu, s, off);
        return s;
    };

    float* out_b = out;
    float* out_c = out + (size_t)NIMG * 4;
    float* out_a = out + (size_t)NIMG * 14;

    float l0 = dot(w1) + b1[0];
    float l1 = dot(w1 + 256) + b1[1];
    float mx = fmaxf(l0, l1);
    float e0 = expf(l0 - mx), e1 = expf(l1 - mx);
    float inv = 1.f / (e0 + e1);
    if (lane == 0) {
        out_a[warp * 2 + 0] = e0 * inv;
        out_a[warp * 2 + 1] = e1 * inv;
    }
#pragma unroll
    for (int o = 0; o < 4; o++) {
        float v = dot(w2 + o * 256) + b2[o];
        if (lane == 0) out_b[warp * 4 + o] = v;
    }
#pragma unroll
    for (int o = 0; o < 10; o++) {
        float v = dot(w3 + o * 256) + b3[o];
        if (lane == 0) out_c[warp * 10 + o] = v;
    }
}

// ---------------------------------------------------------------------------
extern "C" void kernel_launch(void* const* d_in, const int* in_sizes, int n_in,
                              void* d_out, int out_size)
{
    const float* x    = (const float*)d_in[0];
    const float* c1w  = (const float*)d_in[1];
    const float* c1b  = (const float*)d_in[2];
    const float* a1   = (const float*)d_in[3];
    const float* c2w  = (const float*)d_in[4];
    const float* c2b  = (const float*)d_in[5];
    const float* a2   = (const float*)d_in[6];
    const float* c3w  = (const float*)d_in[7];
    const float* c3b  = (const float*)d_in[8];
    const float* a3   = (const float*)d_in[9];
    const float* c4w  = (const float*)d_in[10];
    const float* c4b  = (const float*)d_in[11];
    const float* a4   = (const float*)d_in[12];
    const float* d5w  = (const float*)d_in[13];
    const float* d5b  = (const float*)d_in[14];
    const float* a5   = (const float*)d_in[15];
    const float* d61w = (const float*)d_in[16];
    const float* d61b = (const float*)d_in[17];
    const float* d62w = (const float*)d_in[18];
    const float* d62b = (const float*)d_in[19];
    const float* d63w = (const float*)d_in[20];
    const float* d63b = (const float*)d_in[21];
    float* out = (float*)d_out;

    cudaFuncSetAttribute(k1_conv1_pool, cudaFuncAttributeMaxDynamicSharedMemorySize,
                         K1_SMEM_FLOATS * 4);
    cudaFuncSetAttribute(k2_conv2_pool, cudaFuncAttributeMaxDynamicSharedMemorySize,
                         K2_SMEM_FLOATS * 4);
    cudaFuncSetAttribute(k4_conv3_pool, cudaFuncAttributeMaxDynamicSharedMemorySize,
                         K4_SMEM_FLOATS * 4);
    cudaFuncSetAttribute(k6_conv4, cudaFuncAttributeMaxDynamicSharedMemorySize,
                         K6_SMEM_FLOATS * 4);

    k1_conv1_pool<<<dim3(NIMG, 4), 288, K1_SMEM_FLOATS * 4>>>(x, c1w, c1b, a1);
    k2_conv2_pool<<<NIMG, 448, K2_SMEM_FLOATS * 4>>>(c2w, c2b, a2);
    k4_conv3_pool<<<NIMG / 4, 256, K4_SMEM_FLOATS * 4>>>(c3w, c3b, a3);
    k6_conv4<<<dim3(NIMG / 8, 2), 256, K6_SMEM_FLOATS * 4>>>(c4w, c4b, a4);
    k7_fc5<<<dim3(32, 4), 256>>>(d5w, d5b, a5);
    k8_heads<<<(NIMG * 32) / 256, 256>>>(d61w, d61b, d62w, d62b, d63w, d63b, out);
}